// round 13
// baseline (speedup 1.0000x reference)
#include <cuda_runtime.h>
#include <cstdint>

// Problem constants
#define N_TOK   4096
#define D_MODEL 768
#define N_HEADS 12
#define D_K     64
#define KV_SPLIT 4
#define SPLIT_LEN (N_TOK / KV_SPLIT)   // 1024

// ---------------------------------------------------------------------------
// Scratch buffers (float-typed; several hold tf32-rounded bit patterns)
// ---------------------------------------------------------------------------
__device__ float g_q[N_HEADS * N_TOK * D_K];            // tf32 bits, pre-scaled 0.125*log2e
__device__ float g_k[N_HEADS * N_TOK * D_K];            // tf32 bits, [h][tok][dk]
__device__ float g_v[N_HEADS * D_K * N_TOK];            // tf32 bits, TRANSPOSED [h][dk][tok]
__device__ float g_attn[N_TOK * D_MODEL];               // tf32 bits (combine output)
__device__ float g_xc[3][N_TOK * D_MODEL];              // converted inputs Q,K,V
__device__ float g_wc[4][D_MODEL * D_MODEL];            // converted Wq,Wk,Wv,Wo
__device__ float g_op[KV_SPLIT][N_TOK * D_MODEL];       // partial O (unnormalized)
__device__ float g_lp[KV_SPLIT][N_HEADS * N_TOK];       // partial row sums

// ---------------------------------------------------------------------------
// Helpers (baseline sm_80+ PTX only)
// ---------------------------------------------------------------------------
__device__ __forceinline__ uint32_t f2tf32(float f) {
    uint32_t o;
    asm("cvt.rna.tf32.f32 %0, %1;" : "=r"(o) : "f"(f));
    return o;
}
__device__ __forceinline__ float f2tf32f(float f) {
    return __uint_as_float(f2tf32(f));
}
__device__ __forceinline__ float ex2f(float x) {
    float r;
    asm("ex2.approx.f32 %0, %1;" : "=f"(r) : "f"(x));
    return r;
}
__device__ __forceinline__ uint32_t smem_u32(const void* p) {
    uint32_t a;
    asm("{ .reg .u64 t; cvta.to.shared.u64 t, %1; cvt.u32.u64 %0, t; }" : "=r"(a) : "l"(p));
    return a;
}
#define CP_ASYNC16(dst_u32, src) \
    asm volatile("cp.async.cg.shared.global [%0], [%1], 16;" \
                 :: "r"(dst_u32), "l"(src) : "memory")
#define CP_COMMIT() asm volatile("cp.async.commit_group;" ::: "memory")
#define CP_WAIT1()  asm volatile("cp.async.wait_group 1;" ::: "memory")
#define CP_WAIT0()  asm volatile("cp.async.wait_group 0;" ::: "memory")

__device__ __forceinline__ void ldsm_x4(uint32_t& r0, uint32_t& r1,
                                        uint32_t& r2, uint32_t& r3, uint32_t addr) {
    asm volatile("ldmatrix.sync.aligned.m8n8.x4.shared.b16 {%0,%1,%2,%3}, [%4];"
                 : "=r"(r0), "=r"(r1), "=r"(r2), "=r"(r3) : "r"(addr));
}

// D(16x8) += A(16x8) * B(8x8); A row-major, B col-major; fp32 accum.
__device__ __forceinline__ void mma_tf32(float c[4], const uint32_t a[4],
                                         const uint32_t b[2]) {
    asm volatile(
        "mma.sync.aligned.m16n8k8.row.col.f32.tf32.tf32.f32 "
        "{%0,%1,%2,%3}, {%4,%5,%6,%7}, {%8,%9}, {%0,%1,%2,%3};"
        : "+f"(c[0]), "+f"(c[1]), "+f"(c[2]), "+f"(c[3])
        : "r"(a[0]), "r"(a[1]), "r"(a[2]), "r"(a[3]), "r"(b[0]), "r"(b[1]));
}

// ---------------------------------------------------------------------------
// Fused tf32 pre-conversion: inputs (y=0..2) and weights (y=0..3)
// ---------------------------------------------------------------------------
#define NX4 (N_TOK * D_MODEL / 4)
#define NW4 (D_MODEL * D_MODEL / 4)

__global__ void cvt_inputs_kernel(const float4* __restrict__ a,
                                  const float4* __restrict__ b,
                                  const float4* __restrict__ cc,
                                  float4* __restrict__ dst)
{
    int i = blockIdx.x * blockDim.x + threadIdx.x;
    if (i >= NX4) return;
    const float4* src = (blockIdx.y == 0) ? a : (blockIdx.y == 1) ? b : cc;
    float4 t = src[i];
    t.x = f2tf32f(t.x); t.y = f2tf32f(t.y);
    t.z = f2tf32f(t.z); t.w = f2tf32f(t.w);
    dst[(size_t)blockIdx.y * NX4 + i] = t;
}
__global__ void cvt_weights_kernel(const float4* __restrict__ a,
                                   const float4* __restrict__ b,
                                   const float4* __restrict__ cc,
                                   const float4* __restrict__ d,
                                   float4* __restrict__ dst)
{
    int i = blockIdx.x * blockDim.x + threadIdx.x;
    if (i >= NW4) return;
    const float4* src = (blockIdx.y == 0) ? a : (blockIdx.y == 1) ? b
                      : (blockIdx.y == 2) ? cc : d;
    float4 t = src[i];
    t.x = f2tf32f(t.x); t.y = f2tf32f(t.y);
    t.z = f2tf32f(t.z); t.w = f2tf32f(t.w);
    dst[(size_t)blockIdx.y * NW4 + i] = t;
}

// ---------------------------------------------------------------------------
// GEMM mainloop (shared): block 128x128x32, 8 warps (2x4), warp tile 64x32,
// cp.async double-buffered, operands pre-converted tf32 bits (no cvt in loop).
// ---------------------------------------------------------------------------
#define GBM 128
#define GBN 128
#define GBK 32
#define GST 36
#define GEMM_SMEM_BYTES (2 * 2 * GBM * GST * 4)
#define GEMM_NIT (D_MODEL / GBK)   // 24

#define GEMM_PREFETCH(as_, bs_, Xp_, Wp_, k0_) \
    do { \
        for (int i_ = tid; i_ < 1024; i_ += 256) { \
            int r_ = i_ >> 3, c4_ = (i_ & 7) * 4; \
            CP_ASYNC16((as_) + (r_ * GST + c4_) * 4, (Xp_) + (size_t)r_ * D_MODEL + (k0_) + c4_); \
            CP_ASYNC16((bs_) + (r_ * GST + c4_) * 4, (Wp_) + (size_t)r_ * D_MODEL + (k0_) + c4_); \
        } \
        CP_COMMIT(); \
    } while (0)

#define GEMM_MAINLOOP(Xp_, Wp_) \
    { \
        uint32_t as0 = sbase, bs0 = sbase + GBM * GST * 4; \
        GEMM_PREFETCH(as0, bs0, Xp_, Wp_, 0); \
    } \
    for (int it = 0; it < GEMM_NIT; ++it) { \
        const int cur = it & 1; \
        if (it + 1 < GEMM_NIT) { \
            uint32_t as_ = sbase + (uint32_t)(cur ^ 1) * 2 * GBM * GST * 4; \
            uint32_t bs_ = as_ + GBM * GST * 4; \
            GEMM_PREFETCH(as_, bs_, Xp_, Wp_, (it + 1) * GBK); \
            CP_WAIT1(); \
        } else { \
            CP_WAIT0(); \
        } \
        __syncthreads(); \
        const uint32_t* As = gsh + (size_t)cur * 2 * GBM * GST; \
        const uint32_t* Bs = As + GBM * GST; \
        _Pragma("unroll") \
        for (int s = 0; s < 4; s++) { \
            const int c0 = s * 8; \
            uint32_t a[4][4], b[4][2]; \
            _Pragma("unroll") \
            for (int mt = 0; mt < 4; mt++) { \
                int r = wm * 64 + mt * 16 + g; \
                a[mt][0] = As[r * GST + c0 + c]; \
                a[mt][1] = As[(r + 8) * GST + c0 + c]; \
                a[mt][2] = As[r * GST + c0 + c + 4]; \
                a[mt][3] = As[(r + 8) * GST + c0 + c + 4]; \
            } \
            _Pragma("unroll") \
            for (int nt = 0; nt < 4; nt++) { \
                int n = wn * 32 + nt * 8 + g; \
                b[nt][0] = Bs[n * GST + c0 + c]; \
                b[nt][1] = Bs[n * GST + c0 + c + 4]; \
            } \
            _Pragma("unroll") \
            for (int mt = 0; mt < 4; mt++) \
                _Pragma("unroll") \
                for (int nt = 0; nt < 4; nt++) \
                    mma_tf32(acc[mt][nt], a[mt], b[nt]); \
        } \
        __syncthreads(); \
    }

// ---------------------------------------------------------------------------
// Fused QKV projection. Grid (6, 32, 3). z=0: q (scaled by 0.125*log2e,
// [h][tok][dk]), z=1: k ([h][tok][dk]), z=2: v TRANSPOSED ([h][dk][tok]).
// ---------------------------------------------------------------------------
#define QSCALE 0.18033688011112042f   // 0.125 * log2(e)

__global__ void __launch_bounds__(256) qkv_gemm_kernel(
    const float* __restrict__ x0, const float* __restrict__ x1, const float* __restrict__ x2,
    const float* __restrict__ w0, const float* __restrict__ w1, const float* __restrict__ w2,
    const float* __restrict__ bq_, const float* __restrict__ bk_, const float* __restrict__ bv_,
    float* __restrict__ o0, float* __restrict__ o1, float* __restrict__ o2)
{
    extern __shared__ uint32_t gsh[];
    const int tid  = threadIdx.x;
    const int wid  = tid >> 5;
    const int lane = tid & 31;
    const int g    = lane >> 2;
    const int c    = lane & 3;
    const int wm   = wid >> 2;
    const int wn   = wid & 3;
    const int m0   = blockIdx.y * GBM;
    const int n0   = blockIdx.x * GBN;
    const int z    = blockIdx.z;

    const float* X    = (z == 0) ? x0 : (z == 1) ? x1 : x2;
    const float* W    = (z == 0) ? w0 : (z == 1) ? w1 : w2;
    const float* bias = (z == 0) ? bq_ : (z == 1) ? bk_ : bv_;
    const float scale = (z == 0) ? QSCALE : 1.0f;

    const uint32_t sbase = smem_u32(gsh);
    const float* Xp = X + (size_t)m0 * D_MODEL;
    const float* Wp = W + (size_t)n0 * D_MODEL;

    float acc[4][4][4];
#pragma unroll
    for (int i = 0; i < 4; i++)
#pragma unroll
        for (int j = 0; j < 4; j++)
#pragma unroll
            for (int f = 0; f < 4; f++) acc[i][j][f] = 0.0f;

    GEMM_MAINLOOP(Xp, Wp)

#pragma unroll
    for (int nt = 0; nt < 4; nt++) {
        int col = n0 + wn * 32 + nt * 8 + 2 * c;
        float b0 = bias[col], b1 = bias[col + 1];
        int h = col >> 6, t = col & 63;
#pragma unroll
        for (int mt = 0; mt < 4; mt++) {
            int row = m0 + wm * 64 + mt * 16 + g;
            float v00 = f2tf32f((acc[mt][nt][0] + b0) * scale);
            float v01 = f2tf32f((acc[mt][nt][1] + b1) * scale);
            float v10 = f2tf32f((acc[mt][nt][2] + b0) * scale);
            float v11 = f2tf32f((acc[mt][nt][3] + b1) * scale);
            if (z == 2) {
                float* vp = o2;  // transposed: [h][dk][tok]
                vp[((size_t)h * D_K + t)     * N_TOK + row]     = v00;
                vp[((size_t)h * D_K + t + 1) * N_TOK + row]     = v01;
                vp[((size_t)h * D_K + t)     * N_TOK + row + 8] = v10;
                vp[((size_t)h * D_K + t + 1) * N_TOK + row + 8] = v11;
            } else {
                float* outp = (z == 0) ? o0 : o1;
                *(float2*)&outp[((size_t)h * N_TOK + row) * D_K + t]     = make_float2(v00, v01);
                *(float2*)&outp[((size_t)h * N_TOK + row + 8) * D_K + t] = make_float2(v10, v11);
            }
        }
    }
}

// ---------------------------------------------------------------------------
// Output projection
// ---------------------------------------------------------------------------
__global__ void __launch_bounds__(256) gemm_o_kernel(
    const float* __restrict__ X, const float* __restrict__ W,
    const float* __restrict__ bias, float* __restrict__ out)
{
    extern __shared__ uint32_t gsh[];
    const int tid  = threadIdx.x;
    const int wid  = tid >> 5;
    const int lane = tid & 31;
    const int g    = lane >> 2;
    const int c    = lane & 3;
    const int wm   = wid >> 2;
    const int wn   = wid & 3;
    const int m0   = blockIdx.y * GBM;
    const int n0   = blockIdx.x * GBN;

    const uint32_t sbase = smem_u32(gsh);
    const float* Xp = X + (size_t)m0 * D_MODEL;
    const float* Wp = W + (size_t)n0 * D_MODEL;

    float acc[4][4][4];
#pragma unroll
    for (int i = 0; i < 4; i++)
#pragma unroll
        for (int j = 0; j < 4; j++)
#pragma unroll
            for (int f = 0; f < 4; f++) acc[i][j][f] = 0.0f;

    GEMM_MAINLOOP(Xp, Wp)

#pragma unroll
    for (int nt = 0; nt < 4; nt++) {
        int col = n0 + wn * 32 + nt * 8 + 2 * c;
        float b0 = bias[col], b1 = bias[col + 1];
#pragma unroll
        for (int mt = 0; mt < 4; mt++) {
            int row = m0 + wm * 64 + mt * 16 + g;
            *(float2*)&out[(size_t)row * D_MODEL + col] =
                make_float2(acc[mt][nt][0] + b0, acc[mt][nt][1] + b1);
            *(float2*)&out[(size_t)(row + 8) * D_MODEL + col] =
                make_float2(acc[mt][nt][2] + b0, acc[mt][nt][3] + b1);
        }
    }
}

// ---------------------------------------------------------------------------
// Flash attention, split-KV, ldmatrix loads, 2 m-tiles/warp, split S-chains.
// Grid (32, 12, KV_SPLIT), 128 threads (4 warps x 32 q-rows). kv tiles of 64.
// smem: Qp[128*68] (Q then P), Ks 2x[64*68] ([kv][dk]), Vt 2x[64*68] ([dk][kv]).
// ---------------------------------------------------------------------------
#define AST 68
#define VST2 68
#define ATT_QW   (128 * AST)
#define ATT_KW   (64 * AST)
#define ATT_VW   (64 * VST2)
#define ATT_SMEM_BYTES ((ATT_QW + 2 * ATT_KW + 2 * ATT_VW) * 4)
#define ATT_THREADS 128

__global__ void __launch_bounds__(ATT_THREADS, 2) attn_tc_kernel(
    const float* __restrict__ q, const float* __restrict__ k,
    const float* __restrict__ v, float* __restrict__ opart,
    float* __restrict__ lpart)
{
    extern __shared__ uint32_t sh[];
    uint32_t* Qp  = sh;
    uint32_t* Ksb[2] = { sh + ATT_QW, sh + ATT_QW + ATT_KW };
    uint32_t* Vsb[2] = { sh + ATT_QW + 2 * ATT_KW, sh + ATT_QW + 2 * ATT_KW + ATT_VW };

    const int tid  = threadIdx.x;
    const int wid  = tid >> 5;
    const int lane = tid & 31;
    const int g    = lane >> 2;
    const int c    = lane & 3;
    const int wr   = wid * 32;         // this warp's 32-row block
    const int h    = blockIdx.y;
    const int q0   = blockIdx.x * 128;
    const int sp   = blockIdx.z;

    float* op = opart + (size_t)sp * N_TOK * D_MODEL;
    float* lp = lpart + (size_t)sp * N_HEADS * N_TOK;

    const float* kh = k + ((size_t)h * N_TOK + sp * SPLIT_LEN) * D_K;   // [tok][dk]
    const float* vh = v + (size_t)h * D_K * N_TOK + sp * SPLIT_LEN;     // [dk][tok]

    // ldmatrix per-lane address components (bytes)
    const int m_ = lane >> 3, r_ = lane & 7;
    const uint32_t QpA = smem_u32(Qp);
    const uint32_t KsA0 = smem_u32(Ksb[0]), KsA1 = smem_u32(Ksb[1]);
    const uint32_t VsA0 = smem_u32(Vsb[0]), VsA1 = smem_u32(Vsb[1]);
    const uint32_t kOff = (uint32_t)(r_ * AST + 4 * m_) * 4;
    const uint32_t pOff = (uint32_t)(((m_ & 1) * 8 + r_) * AST + (m_ >> 1) * 4) * 4;
    const uint32_t vOff = (uint32_t)(((m_ >> 1) * 8 + r_) * VST2 + 4 * (m_ & 1)) * 4;

    // Prefetch kv tile 0.
    {
        uint32_t ks = KsA0, vs = VsA0;
#pragma unroll
        for (int i = tid; i < 1024; i += ATT_THREADS) {
            int r = i >> 4, c4 = (i & 15) * 4;
            CP_ASYNC16(ks + (r * AST + c4) * 4, kh + (size_t)r * D_K + c4);
            CP_ASYNC16(vs + (r * VST2 + c4) * 4, vh + (size_t)r * N_TOK + c4);
        }
        CP_COMMIT();
    }

    // Q tile: already scaled + tf32 bits -> plain copy.
    const float* qh = q + ((size_t)h * N_TOK + q0) * D_K;
#pragma unroll
    for (int i = tid; i < 2048; i += ATT_THREADS) {
        int r = i >> 4, c4 = (i & 15) * 4;
        uint4 t = *(const uint4*)(qh + (size_t)r * D_K + c4);
        *(uint4*)&Qp[r * AST + c4] = t;
    }
    __syncthreads();

    // Persistent Q fragments: 2 m-tiles x 8 k-steps.
    uint32_t qa[2][8][4];
#pragma unroll
    for (int mt = 0; mt < 2; mt++) {
        int rb = wr + mt * 16;
#pragma unroll
        for (int s = 0; s < 8; s++) {
            int c0 = s * 8;
            qa[mt][s][0] = Qp[(rb + g) * AST + c0 + c];
            qa[mt][s][1] = Qp[(rb + g + 8) * AST + c0 + c];
            qa[mt][s][2] = Qp[(rb + g) * AST + c0 + c + 4];
            qa[mt][s][3] = Qp[(rb + g + 8) * AST + c0 + c + 4];
        }
    }
    __syncthreads();  // Q fully read before Qp is reused as P

    float o[2][8][4];
#pragma unroll
    for (int mt = 0; mt < 2; mt++)
#pragma unroll
        for (int nt = 0; nt < 8; nt++)
#pragma unroll
            for (int f = 0; f < 4; f++) o[mt][nt][f] = 0.0f;
    float ls[4] = {0.0f, 0.0f, 0.0f, 0.0f};   // [mt*2 + (0:row g,1:row g+8)]

    const int NIT = SPLIT_LEN / 64;  // 16
    for (int it = 0; it < NIT; ++it) {
        const int cur = it & 1;
        if (it + 1 < NIT) {
            const int kt = (it + 1) * 64;
            uint32_t ks = cur ? KsA0 : KsA1;
            uint32_t vs = cur ? VsA0 : VsA1;
#pragma unroll
            for (int i = tid; i < 1024; i += ATT_THREADS) {
                int r = i >> 4, c4 = (i & 15) * 4;
                CP_ASYNC16(ks + (r * AST + c4) * 4, kh + (size_t)(kt + r) * D_K + c4);
                CP_ASYNC16(vs + (r * VST2 + c4) * 4, vh + (size_t)r * N_TOK + kt + c4);
            }
            CP_COMMIT();
            CP_WAIT1();
        } else {
            CP_WAIT0();
        }
        __syncthreads();

        const uint32_t KsA = cur ? KsA1 : KsA0;
        const uint32_t VsA = cur ? VsA1 : VsA0;

        // S = Q.K^T, SPLIT accumulation chains (s 0..3 / 4..7); exp2; P -> Qp.
#pragma unroll
        for (int nt = 0; nt < 8; nt++) {
            uint32_t bb[8][2];
            const uint32_t kb = KsA + kOff + (uint32_t)nt * (8 * AST * 4);
#pragma unroll
            for (int j = 0; j < 4; j++)
                ldsm_x4(bb[2 * j][0], bb[2 * j][1], bb[2 * j + 1][0], bb[2 * j + 1][1],
                        kb + (uint32_t)j * 64);
#pragma unroll
            for (int mt = 0; mt < 2; mt++) {
                float sA[4] = {0.0f, 0.0f, 0.0f, 0.0f};
                float sB[4] = {0.0f, 0.0f, 0.0f, 0.0f};
#pragma unroll
                for (int s = 0; s < 4; s++) {
                    mma_tf32(sA, qa[mt][s], bb[s]);
                    mma_tf32(sB, qa[mt][s + 4], bb[s + 4]);
                }
                float p0 = ex2f(sA[0] + sB[0]);
                float p1 = ex2f(sA[1] + sB[1]);
                float p2 = ex2f(sA[2] + sB[2]);
                float p3 = ex2f(sA[3] + sB[3]);
                ls[mt * 2]     += p0 + p1;
                ls[mt * 2 + 1] += p2 + p3;
                int rb = wr + mt * 16;
                int col = nt * 8 + 2 * c;
                *(uint2*)&Qp[(rb + g) * AST + col]     = make_uint2(f2tf32(p0), f2tf32(p1));
                *(uint2*)&Qp[(rb + g + 8) * AST + col] = make_uint2(f2tf32(p2), f2tf32(p3));
            }
        }
        __syncwarp();  // P rows are warp-private

        // O += P.V  (each V B-frag reused by both m-tiles)
#pragma unroll
        for (int s = 0; s < 8; s++) {
            uint32_t pa[2][4];
#pragma unroll
            for (int mt = 0; mt < 2; mt++)
                ldsm_x4(pa[mt][0], pa[mt][1], pa[mt][2], pa[mt][3],
                        QpA + pOff + (uint32_t)((wr + mt * 16) * AST) * 4 + (uint32_t)s * 32);
            const uint32_t vb = VsA + vOff + (uint32_t)s * 32;
#pragma unroll
            for (int j = 0; j < 4; j++) {
                uint32_t b0, b1, b2, b3;
                ldsm_x4(b0, b1, b2, b3, vb + (uint32_t)j * (16 * VST2 * 4));
                uint32_t bA[2] = {b0, b1}, bB[2] = {b2, b3};
#pragma unroll
                for (int mt = 0; mt < 2; mt++) {
                    mma_tf32(o[mt][2 * j], pa[mt], bA);
                    mma_tf32(o[mt][2 * j + 1], pa[mt], bB);
                }
            }
        }
        __syncthreads();  // all reads of buf[cur] done before next prefetch
    }

    // Row sums across the 4-lane quad; write l and O for both m-tiles.
#pragma unroll
    for (int i = 0; i < 4; i++) {
        ls[i] += __shfl_xor_sync(0xffffffffu, ls[i], 1);
        ls[i] += __shfl_xor_sync(0xffffffffu, ls[i], 2);
    }
    if (c == 0) {
#pragma unroll
        for (int mt = 0; mt < 2; mt++) {
            lp[(size_t)h * N_TOK + q0 + wr + mt * 16 + g]     = ls[mt * 2];
            lp[(size_t)h * N_TOK + q0 + wr + mt * 16 + g + 8] = ls[mt * 2 + 1];
        }
    }

#pragma unroll
    for (int mt = 0; mt < 2; mt++) {
        int rb = q0 + wr + mt * 16;
#pragma unroll
        for (int nt = 0; nt < 8; nt++) {
            int col = h * D_K + nt * 8 + 2 * c;
            *(float2*)&op[(size_t)(rb + g) * D_MODEL + col] =
                make_float2(o[mt][nt][0], o[mt][nt][1]);
            *(float2*)&op[(size_t)(rb + g + 8) * D_MODEL + col] =
                make_float2(o[mt][nt][2], o[mt][nt][3]);
        }
    }
}

// ---------------------------------------------------------------------------
// Combine: attn = tf32(sum_sp O_sp / sum_sp l_sp)
// ---------------------------------------------------------------------------
__global__ void combine_kernel(const float* __restrict__ opart,
                               const float* __restrict__ lpart,
                               float* __restrict__ out)
{
    int i = blockIdx.x * blockDim.x + threadIdx.x;   // float4 index
    if (i >= N_TOK * D_MODEL / 4) return;
    int r  = i / (D_MODEL / 4);
    int c4 = (i % (D_MODEL / 4)) * 4;
    int h  = c4 >> 6;
    float l = 0.0f;
    float4 a = make_float4(0.0f, 0.0f, 0.0f, 0.0f);
#pragma unroll
    for (int sp = 0; sp < KV_SPLIT; sp++) {
        l += lpart[(size_t)sp * N_HEADS * N_TOK + (size_t)h * N_TOK + r];
        float4 t = ((const float4*)(opart + (size_t)sp * N_TOK * D_MODEL))[i];
        a.x += t.x; a.y += t.y; a.z += t.z; a.w += t.w;
    }
    float inv = 1.0f / l;
    float4 o;
    o.x = f2tf32f(a.x * inv); o.y = f2tf32f(a.y * inv);
    o.z = f2tf32f(a.z * inv); o.w = f2tf32f(a.w * inv);
    ((float4*)out)[i] = o;
}

// ---------------------------------------------------------------------------
// Launch
// ---------------------------------------------------------------------------
extern "C" void kernel_launch(void* const* d_in, const int* in_sizes, int n_in,
                              void* d_out, int out_size)
{
    const float* Q  = (const float*)d_in[0];
    const float* K  = (const float*)d_in[1];
    const float* V  = (const float*)d_in[2];
    const float* Wq = (const float*)d_in[3];
    const float* bq = (const float*)d_in[4];
    const float* Wk = (const float*)d_in[5];
    const float* bk = (const float*)d_in[6];
    const float* Wv = (const float*)d_in[7];
    const float* bv = (const float*)d_in[8];
    const float* Wo = (const float*)d_in[9];
    const float* bo = (const float*)d_in[10];
    float* out = (float*)d_out;

    float *qb, *kb, *vb, *ab, *xc, *wc, *op, *lp;
    cudaGetSymbolAddress((void**)&qb, g_q);
    cudaGetSymbolAddress((void**)&kb, g_k);
    cudaGetSymbolAddress((void**)&vb, g_v);
    cudaGetSymbolAddress((void**)&ab, g_attn);
    cudaGetSymbolAddress((void**)&xc, g_xc);
    cudaGetSymbolAddress((void**)&wc, g_wc);
    cudaGetSymbolAddress((void**)&op, g_op);
    cudaGetSymbolAddress((void**)&lp, g_lp);

    float* xc0 = xc;
    float* xc1 = xc + (size_t)N_TOK * D_MODEL;
    float* xc2 = xc + 2 * (size_t)N_TOK * D_MODEL;
    float* wc0 = wc;
    float* wc1 = wc + (size_t)D_MODEL * D_MODEL;
    float* wc2 = wc + 2 * (size_t)D_MODEL * D_MODEL;
    float* wc3 = wc + 3 * (size_t)D_MODEL * D_MODEL;

    // Idempotent, capture-safe (not stream ops).
    cudaFuncSetAttribute(attn_tc_kernel,
                         cudaFuncAttributeMaxDynamicSharedMemorySize, ATT_SMEM_BYTES);
    cudaFuncSetAttribute(qkv_gemm_kernel,
                         cudaFuncAttributeMaxDynamicSharedMemorySize, GEMM_SMEM_BYTES);
    cudaFuncSetAttribute(gemm_o_kernel,
                         cudaFuncAttributeMaxDynamicSharedMemorySize, GEMM_SMEM_BYTES);

    // 1) Pre-convert operands to tf32 (RNA), 2 fused launches.
    dim3 cvtIGrid((NX4 + 255) / 256, 3);
    cvt_inputs_kernel<<<cvtIGrid, 256>>>((const float4*)Q, (const float4*)K,
                                         (const float4*)V, (float4*)xc);
    dim3 cvtWGrid((NW4 + 255) / 256, 4);
    cvt_weights_kernel<<<cvtWGrid, 256>>>((const float4*)Wq, (const float4*)Wk,
                                          (const float4*)Wv, (const float4*)Wo,
                                          (float4*)wc);

    // 2) Fused QKV projections (V written transposed; q scaled by 0.125*log2e).
    dim3 qkvGrid(D_MODEL / GBN, N_TOK / GBM, 3);   // (6, 32, 3)
    qkv_gemm_kernel<<<qkvGrid, 256, GEMM_SMEM_BYTES>>>(
        xc0, xc1, xc2, wc0, wc1, wc2, bq, bk, bv, qb, kb, vb);

    // 3) Split-KV attention (128 threads, 4 warps x 32 rows).
    dim3 attnGrid(N_TOK / 128, N_HEADS, KV_SPLIT); // (32, 12, 4)
    attn_tc_kernel<<<attnGrid, ATT_THREADS, ATT_SMEM_BYTES>>>(qb, kb, vb, op, lp);

    // 4) Combine partials -> g_attn (tf32 bits).
    combine_kernel<<<(NX4 + 255) / 256, 256>>>(op, lp, ab);

    // 5) Output projection.
    dim3 oGrid(D_MODEL / GBN, N_TOK / GBM);        // (6, 32)
    gemm_o_kernel<<<oGrid, 256, GEMM_SMEM_BYTES>>>(ab, wc3, bo, out);
}

// round 14
// speedup vs baseline: 1.0617x; 1.0617x over previous
#include <cuda_runtime.h>
#include <cstdint>

// Problem constants
#define N_TOK   4096
#define D_MODEL 768
#define N_HEADS 12
#define D_K     64
#define KV_SPLIT 4
#define SPLIT_LEN (N_TOK / KV_SPLIT)   // 1024

// ---------------------------------------------------------------------------
// Scratch buffers (float-typed; several hold tf32-rounded bit patterns)
// ---------------------------------------------------------------------------
__device__ float g_q[N_HEADS * N_TOK * D_K];            // tf32 bits, pre-scaled 0.125*log2e
__device__ float g_k[N_HEADS * N_TOK * D_K];            // tf32 bits, [h][tok][dk]
__device__ float g_v[N_HEADS * D_K * N_TOK];            // tf32 bits, TRANSPOSED [h][dk][tok]
__device__ float g_attn[N_TOK * D_MODEL];               // tf32 bits (combine output)
__device__ float g_xc[3][N_TOK * D_MODEL];              // converted inputs Q,K,V
__device__ float g_wc[4][D_MODEL * D_MODEL];            // converted Wq,Wk,Wv,Wo
__device__ float g_op[KV_SPLIT][N_TOK * D_MODEL];       // partial O (unnormalized)
__device__ float g_lp[KV_SPLIT][N_HEADS * N_TOK];       // partial row sums

// ---------------------------------------------------------------------------
// Helpers (baseline sm_80+ PTX only)
// ---------------------------------------------------------------------------
__device__ __forceinline__ uint32_t f2tf32(float f) {
    uint32_t o;
    asm("cvt.rna.tf32.f32 %0, %1;" : "=r"(o) : "f"(f));
    return o;
}
__device__ __forceinline__ float f2tf32f(float f) {
    return __uint_as_float(f2tf32(f));
}
__device__ __forceinline__ float ex2f(float x) {
    float r;
    asm("ex2.approx.f32 %0, %1;" : "=f"(r) : "f"(x));
    return r;
}
__device__ __forceinline__ uint32_t smem_u32(const void* p) {
    uint32_t a;
    asm("{ .reg .u64 t; cvta.to.shared.u64 t, %1; cvt.u32.u64 %0, t; }" : "=r"(a) : "l"(p));
    return a;
}
#define CP_ASYNC16(dst_u32, src) \
    asm volatile("cp.async.cg.shared.global [%0], [%1], 16;" \
                 :: "r"(dst_u32), "l"(src) : "memory")
#define CP_COMMIT() asm volatile("cp.async.commit_group;" ::: "memory")
#define CP_WAIT1()  asm volatile("cp.async.wait_group 1;" ::: "memory")
#define CP_WAIT0()  asm volatile("cp.async.wait_group 0;" ::: "memory")

__device__ __forceinline__ void ldsm_x4(uint32_t& r0, uint32_t& r1,
                                        uint32_t& r2, uint32_t& r3, uint32_t addr) {
    asm volatile("ldmatrix.sync.aligned.m8n8.x4.shared.b16 {%0,%1,%2,%3}, [%4];"
                 : "=r"(r0), "=r"(r1), "=r"(r2), "=r"(r3) : "r"(addr));
}

// D(16x8) += A(16x8) * B(8x8); A row-major, B col-major; fp32 accum.
__device__ __forceinline__ void mma_tf32(float c[4], const uint32_t a[4],
                                         const uint32_t b[2]) {
    asm volatile(
        "mma.sync.aligned.m16n8k8.row.col.f32.tf32.tf32.f32 "
        "{%0,%1,%2,%3}, {%4,%5,%6,%7}, {%8,%9}, {%0,%1,%2,%3};"
        : "+f"(c[0]), "+f"(c[1]), "+f"(c[2]), "+f"(c[3])
        : "r"(a[0]), "r"(a[1]), "r"(a[2]), "r"(a[3]), "r"(b[0]), "r"(b[1]));
}

// ---------------------------------------------------------------------------
// Fused tf32 pre-conversion: inputs (y=0..2) and weights (y=0..3)
// ---------------------------------------------------------------------------
#define NX4 (N_TOK * D_MODEL / 4)
#define NW4 (D_MODEL * D_MODEL / 4)

__global__ void cvt_inputs_kernel(const float4* __restrict__ a,
                                  const float4* __restrict__ b,
                                  const float4* __restrict__ cc,
                                  float4* __restrict__ dst)
{
    int i = blockIdx.x * blockDim.x + threadIdx.x;
    if (i >= NX4) return;
    const float4* src = (blockIdx.y == 0) ? a : (blockIdx.y == 1) ? b : cc;
    float4 t = src[i];
    t.x = f2tf32f(t.x); t.y = f2tf32f(t.y);
    t.z = f2tf32f(t.z); t.w = f2tf32f(t.w);
    dst[(size_t)blockIdx.y * NX4 + i] = t;
}
__global__ void cvt_weights_kernel(const float4* __restrict__ a,
                                   const float4* __restrict__ b,
                                   const float4* __restrict__ cc,
                                   const float4* __restrict__ d,
                                   float4* __restrict__ dst)
{
    int i = blockIdx.x * blockDim.x + threadIdx.x;
    if (i >= NW4) return;
    const float4* src = (blockIdx.y == 0) ? a : (blockIdx.y == 1) ? b
                      : (blockIdx.y == 2) ? cc : d;
    float4 t = src[i];
    t.x = f2tf32f(t.x); t.y = f2tf32f(t.y);
    t.z = f2tf32f(t.z); t.w = f2tf32f(t.w);
    dst[(size_t)blockIdx.y * NW4 + i] = t;
}

// ---------------------------------------------------------------------------
// GEMM mainloop (shared): block 128x128x32, 8 warps (2x4), warp tile 64x32,
// cp.async double-buffered, operands pre-converted tf32 bits (no cvt in loop).
// ---------------------------------------------------------------------------
#define GBM 128
#define GBN 128
#define GBK 32
#define GST 36
#define GEMM_SMEM_BYTES (2 * 2 * GBM * GST * 4)
#define GEMM_NIT (D_MODEL / GBK)   // 24

#define GEMM_PREFETCH(as_, bs_, Xp_, Wp_, k0_) \
    do { \
        for (int i_ = tid; i_ < 1024; i_ += 256) { \
            int r_ = i_ >> 3, c4_ = (i_ & 7) * 4; \
            CP_ASYNC16((as_) + (r_ * GST + c4_) * 4, (Xp_) + (size_t)r_ * D_MODEL + (k0_) + c4_); \
            CP_ASYNC16((bs_) + (r_ * GST + c4_) * 4, (Wp_) + (size_t)r_ * D_MODEL + (k0_) + c4_); \
        } \
        CP_COMMIT(); \
    } while (0)

#define GEMM_MAINLOOP(Xp_, Wp_) \
    { \
        uint32_t as0 = sbase, bs0 = sbase + GBM * GST * 4; \
        GEMM_PREFETCH(as0, bs0, Xp_, Wp_, 0); \
    } \
    for (int it = 0; it < GEMM_NIT; ++it) { \
        const int cur = it & 1; \
        if (it + 1 < GEMM_NIT) { \
            uint32_t as_ = sbase + (uint32_t)(cur ^ 1) * 2 * GBM * GST * 4; \
            uint32_t bs_ = as_ + GBM * GST * 4; \
            GEMM_PREFETCH(as_, bs_, Xp_, Wp_, (it + 1) * GBK); \
            CP_WAIT1(); \
        } else { \
            CP_WAIT0(); \
        } \
        __syncthreads(); \
        const uint32_t* As = gsh + (size_t)cur * 2 * GBM * GST; \
        const uint32_t* Bs = As + GBM * GST; \
        _Pragma("unroll") \
        for (int s = 0; s < 4; s++) { \
            const int c0 = s * 8; \
            uint32_t a[4][4], b[4][2]; \
            _Pragma("unroll") \
            for (int mt = 0; mt < 4; mt++) { \
                int r = wm * 64 + mt * 16 + g; \
                a[mt][0] = As[r * GST + c0 + c]; \
                a[mt][1] = As[(r + 8) * GST + c0 + c]; \
                a[mt][2] = As[r * GST + c0 + c + 4]; \
                a[mt][3] = As[(r + 8) * GST + c0 + c + 4]; \
            } \
            _Pragma("unroll") \
            for (int nt = 0; nt < 4; nt++) { \
                int n = wn * 32 + nt * 8 + g; \
                b[nt][0] = Bs[n * GST + c0 + c]; \
                b[nt][1] = Bs[n * GST + c0 + c + 4]; \
            } \
            _Pragma("unroll") \
            for (int mt = 0; mt < 4; mt++) \
                _Pragma("unroll") \
                for (int nt = 0; nt < 4; nt++) \
                    mma_tf32(acc[mt][nt], a[mt], b[nt]); \
        } \
        __syncthreads(); \
    }

// ---------------------------------------------------------------------------
// Fused QKV projection. Grid (6, 32, 3). z=0: q (scaled by 0.125*log2e,
// [h][tok][dk]), z=1: k ([h][tok][dk]), z=2: v TRANSPOSED ([h][dk][tok]).
// ---------------------------------------------------------------------------
#define QSCALE 0.18033688011112042f   // 0.125 * log2(e)

__global__ void __launch_bounds__(256) qkv_gemm_kernel(
    const float* __restrict__ x0, const float* __restrict__ x1, const float* __restrict__ x2,
    const float* __restrict__ w0, const float* __restrict__ w1, const float* __restrict__ w2,
    const float* __restrict__ bq_, const float* __restrict__ bk_, const float* __restrict__ bv_,
    float* __restrict__ o0, float* __restrict__ o1, float* __restrict__ o2)
{
    extern __shared__ uint32_t gsh[];
    const int tid  = threadIdx.x;
    const int wid  = tid >> 5;
    const int lane = tid & 31;
    const int g    = lane >> 2;
    const int c    = lane & 3;
    const int wm   = wid >> 2;
    const int wn   = wid & 3;
    const int m0   = blockIdx.y * GBM;
    const int n0   = blockIdx.x * GBN;
    const int z    = blockIdx.z;

    const float* X    = (z == 0) ? x0 : (z == 1) ? x1 : x2;
    const float* W    = (z == 0) ? w0 : (z == 1) ? w1 : w2;
    const float* bias = (z == 0) ? bq_ : (z == 1) ? bk_ : bv_;
    const float scale = (z == 0) ? QSCALE : 1.0f;

    const uint32_t sbase = smem_u32(gsh);
    const float* Xp = X + (size_t)m0 * D_MODEL;
    const float* Wp = W + (size_t)n0 * D_MODEL;

    float acc[4][4][4];
#pragma unroll
    for (int i = 0; i < 4; i++)
#pragma unroll
        for (int j = 0; j < 4; j++)
#pragma unroll
            for (int f = 0; f < 4; f++) acc[i][j][f] = 0.0f;

    GEMM_MAINLOOP(Xp, Wp)

#pragma unroll
    for (int nt = 0; nt < 4; nt++) {
        int col = n0 + wn * 32 + nt * 8 + 2 * c;
        float b0 = bias[col], b1 = bias[col + 1];
        int h = col >> 6, t = col & 63;
#pragma unroll
        for (int mt = 0; mt < 4; mt++) {
            int row = m0 + wm * 64 + mt * 16 + g;
            float v00 = f2tf32f((acc[mt][nt][0] + b0) * scale);
            float v01 = f2tf32f((acc[mt][nt][1] + b1) * scale);
            float v10 = f2tf32f((acc[mt][nt][2] + b0) * scale);
            float v11 = f2tf32f((acc[mt][nt][3] + b1) * scale);
            if (z == 2) {
                float* vp = o2;  // transposed: [h][dk][tok]
                vp[((size_t)h * D_K + t)     * N_TOK + row]     = v00;
                vp[((size_t)h * D_K + t + 1) * N_TOK + row]     = v01;
                vp[((size_t)h * D_K + t)     * N_TOK + row + 8] = v10;
                vp[((size_t)h * D_K + t + 1) * N_TOK + row + 8] = v11;
            } else {
                float* outp = (z == 0) ? o0 : o1;
                *(float2*)&outp[((size_t)h * N_TOK + row) * D_K + t]     = make_float2(v00, v01);
                *(float2*)&outp[((size_t)h * N_TOK + row + 8) * D_K + t] = make_float2(v10, v11);
            }
        }
    }
}

// ---------------------------------------------------------------------------
// Output projection
// ---------------------------------------------------------------------------
__global__ void __launch_bounds__(256) gemm_o_kernel(
    const float* __restrict__ X, const float* __restrict__ W,
    const float* __restrict__ bias, float* __restrict__ out)
{
    extern __shared__ uint32_t gsh[];
    const int tid  = threadIdx.x;
    const int wid  = tid >> 5;
    const int lane = tid & 31;
    const int g    = lane >> 2;
    const int c    = lane & 3;
    const int wm   = wid >> 2;
    const int wn   = wid & 3;
    const int m0   = blockIdx.y * GBM;
    const int n0   = blockIdx.x * GBN;

    const uint32_t sbase = smem_u32(gsh);
    const float* Xp = X + (size_t)m0 * D_MODEL;
    const float* Wp = W + (size_t)n0 * D_MODEL;

    float acc[4][4][4];
#pragma unroll
    for (int i = 0; i < 4; i++)
#pragma unroll
        for (int j = 0; j < 4; j++)
#pragma unroll
            for (int f = 0; f < 4; f++) acc[i][j][f] = 0.0f;

    GEMM_MAINLOOP(Xp, Wp)

#pragma unroll
    for (int nt = 0; nt < 4; nt++) {
        int col = n0 + wn * 32 + nt * 8 + 2 * c;
        float b0 = bias[col], b1 = bias[col + 1];
#pragma unroll
        for (int mt = 0; mt < 4; mt++) {
            int row = m0 + wm * 64 + mt * 16 + g;
            *(float2*)&out[(size_t)row * D_MODEL + col] =
                make_float2(acc[mt][nt][0] + b0, acc[mt][nt][1] + b1);
            *(float2*)&out[(size_t)(row + 8) * D_MODEL + col] =
                make_float2(acc[mt][nt][2] + b0, acc[mt][nt][3] + b1);
        }
    }
}

// ---------------------------------------------------------------------------
// Flash attention, split-KV, ldmatrix loads, 2 m-tiles/warp,
// FUSED S/PV software pipeline: PV(s=nt-1) issued between S-MMA(nt) and exp(nt)
// so tensor work covers the MUFU/CVT/STS stretch and LDSM overlaps MMA issue.
// Grid (32, 12, KV_SPLIT), 128 threads (4 warps x 32 q-rows). kv tiles of 64.
// smem: Qp[128*68] (Q then P), Ks 2x[64*68] ([kv][dk]), Vt 2x[64*68] ([dk][kv]).
// ---------------------------------------------------------------------------
#define AST 68
#define VST2 68
#define ATT_QW   (128 * AST)
#define ATT_KW   (64 * AST)
#define ATT_VW   (64 * VST2)
#define ATT_SMEM_BYTES ((ATT_QW + 2 * ATT_KW + 2 * ATT_VW) * 4)
#define ATT_THREADS 128

// PV step s: O[mt] += P[:, 8s:8s+8] . V[8s:8s+8, :]  (P read from Qp smem)
#define PV_STEP(s_) do { \
    uint32_t pa[2][4]; \
    _Pragma("unroll") \
    for (int mt = 0; mt < 2; mt++) \
        ldsm_x4(pa[mt][0], pa[mt][1], pa[mt][2], pa[mt][3], \
                QpA + pOff + (uint32_t)((wr + mt * 16) * AST) * 4 + (uint32_t)(s_) * 32); \
    const uint32_t vb_ = VsA + vOff + (uint32_t)(s_) * 32; \
    _Pragma("unroll") \
    for (int j = 0; j < 4; j++) { \
        uint32_t b0_, b1_, b2_, b3_; \
        ldsm_x4(b0_, b1_, b2_, b3_, vb_ + (uint32_t)j * (16 * VST2 * 4)); \
        uint32_t bA_[2] = {b0_, b1_}, bB_[2] = {b2_, b3_}; \
        _Pragma("unroll") \
        for (int mt = 0; mt < 2; mt++) { \
            mma_tf32(o[mt][2 * j], pa[mt], bA_); \
            mma_tf32(o[mt][2 * j + 1], pa[mt], bB_); \
        } \
    } \
} while (0)

__global__ void __launch_bounds__(ATT_THREADS, 2) attn_tc_kernel(
    const float* __restrict__ q, const float* __restrict__ k,
    const float* __restrict__ v, float* __restrict__ opart,
    float* __restrict__ lpart)
{
    extern __shared__ uint32_t sh[];
    uint32_t* Qp  = sh;
    uint32_t* Ksb[2] = { sh + ATT_QW, sh + ATT_QW + ATT_KW };
    uint32_t* Vsb[2] = { sh + ATT_QW + 2 * ATT_KW, sh + ATT_QW + 2 * ATT_KW + ATT_VW };

    const int tid  = threadIdx.x;
    const int wid  = tid >> 5;
    const int lane = tid & 31;
    const int g    = lane >> 2;
    const int c    = lane & 3;
    const int wr   = wid * 32;         // this warp's 32-row block
    const int h    = blockIdx.y;
    const int q0   = blockIdx.x * 128;
    const int sp   = blockIdx.z;

    float* op = opart + (size_t)sp * N_TOK * D_MODEL;
    float* lp = lpart + (size_t)sp * N_HEADS * N_TOK;

    const float* kh = k + ((size_t)h * N_TOK + sp * SPLIT_LEN) * D_K;   // [tok][dk]
    const float* vh = v + (size_t)h * D_K * N_TOK + sp * SPLIT_LEN;     // [dk][tok]

    // ldmatrix per-lane address components (bytes)
    const int m_ = lane >> 3, r_ = lane & 7;
    const uint32_t QpA = smem_u32(Qp);
    const uint32_t KsA0 = smem_u32(Ksb[0]), KsA1 = smem_u32(Ksb[1]);
    const uint32_t VsA0 = smem_u32(Vsb[0]), VsA1 = smem_u32(Vsb[1]);
    const uint32_t kOff = (uint32_t)(r_ * AST + 4 * m_) * 4;
    const uint32_t pOff = (uint32_t)(((m_ & 1) * 8 + r_) * AST + (m_ >> 1) * 4) * 4;
    const uint32_t vOff = (uint32_t)(((m_ >> 1) * 8 + r_) * VST2 + 4 * (m_ & 1)) * 4;

    // Prefetch kv tile 0.
    {
        uint32_t ks = KsA0, vs = VsA0;
#pragma unroll
        for (int i = tid; i < 1024; i += ATT_THREADS) {
            int r = i >> 4, c4 = (i & 15) * 4;
            CP_ASYNC16(ks + (r * AST + c4) * 4, kh + (size_t)r * D_K + c4);
            CP_ASYNC16(vs + (r * VST2 + c4) * 4, vh + (size_t)r * N_TOK + c4);
        }
        CP_COMMIT();
    }

    // Q tile: already scaled + tf32 bits -> plain copy.
    const float* qh = q + ((size_t)h * N_TOK + q0) * D_K;
#pragma unroll
    for (int i = tid; i < 2048; i += ATT_THREADS) {
        int r = i >> 4, c4 = (i & 15) * 4;
        uint4 t = *(const uint4*)(qh + (size_t)r * D_K + c4);
        *(uint4*)&Qp[r * AST + c4] = t;
    }
    __syncthreads();

    // Persistent Q fragments: 2 m-tiles x 8 k-steps.
    uint32_t qa[2][8][4];
#pragma unroll
    for (int mt = 0; mt < 2; mt++) {
        int rb = wr + mt * 16;
#pragma unroll
        for (int s = 0; s < 8; s++) {
            int c0 = s * 8;
            qa[mt][s][0] = Qp[(rb + g) * AST + c0 + c];
            qa[mt][s][1] = Qp[(rb + g + 8) * AST + c0 + c];
            qa[mt][s][2] = Qp[(rb + g) * AST + c0 + c + 4];
            qa[mt][s][3] = Qp[(rb + g + 8) * AST + c0 + c + 4];
        }
    }
    __syncthreads();  // Q fully read before Qp is reused as P

    float o[2][8][4];
#pragma unroll
    for (int mt = 0; mt < 2; mt++)
#pragma unroll
        for (int nt = 0; nt < 8; nt++)
#pragma unroll
            for (int f = 0; f < 4; f++) o[mt][nt][f] = 0.0f;
    float ls[4] = {0.0f, 0.0f, 0.0f, 0.0f};   // [mt*2 + (0:row g,1:row g+8)]

    const int NIT = SPLIT_LEN / 64;  // 16
    for (int it = 0; it < NIT; ++it) {
        const int cur = it & 1;
        if (it + 1 < NIT) {
            const int kt = (it + 1) * 64;
            uint32_t ks = cur ? KsA0 : KsA1;
            uint32_t vs = cur ? VsA0 : VsA1;
#pragma unroll
            for (int i = tid; i < 1024; i += ATT_THREADS) {
                int r = i >> 4, c4 = (i & 15) * 4;
                CP_ASYNC16(ks + (r * AST + c4) * 4, kh + (size_t)(kt + r) * D_K + c4);
                CP_ASYNC16(vs + (r * VST2 + c4) * 4, vh + (size_t)r * N_TOK + kt + c4);
            }
            CP_COMMIT();
            CP_WAIT1();
        } else {
            CP_WAIT0();
        }
        __syncthreads();

        const uint32_t KsA = cur ? KsA1 : KsA0;
        const uint32_t VsA = cur ? VsA1 : VsA0;

        // Fused pipeline: per nt, S(nt) MMAs, then PV(nt-1) MMAs (covering the
        // exp stall on S(nt) results), then exp/cvt/store P(nt).
#pragma unroll
        for (int nt = 0; nt < 8; nt++) {
            uint32_t bb[8][2];
            const uint32_t kb = KsA + kOff + (uint32_t)nt * (8 * AST * 4);
#pragma unroll
            for (int j = 0; j < 4; j++)
                ldsm_x4(bb[2 * j][0], bb[2 * j][1], bb[2 * j + 1][0], bb[2 * j + 1][1],
                        kb + (uint32_t)j * 64);

            float s0A[4] = {0.0f, 0.0f, 0.0f, 0.0f};
            float s0B[4] = {0.0f, 0.0f, 0.0f, 0.0f};
            float s1A[4] = {0.0f, 0.0f, 0.0f, 0.0f};
            float s1B[4] = {0.0f, 0.0f, 0.0f, 0.0f};
#pragma unroll
            for (int s = 0; s < 4; s++) {
                mma_tf32(s0A, qa[0][s], bb[s]);
                mma_tf32(s0B, qa[0][s + 4], bb[s + 4]);
                mma_tf32(s1A, qa[1][s], bb[s]);
                mma_tf32(s1B, qa[1][s + 4], bb[s + 4]);
            }

            // PV for previous nt: independent tensor work that executes while
            // the exp below waits on the S MMAs above.
            if (nt > 0) PV_STEP(nt - 1);

            // exp2 + row-sum + store P (tf32) into Qp
            {
                float p0 = ex2f(s0A[0] + s0B[0]);
                float p1 = ex2f(s0A[1] + s0B[1]);
                float p2 = ex2f(s0A[2] + s0B[2]);
                float p3 = ex2f(s0A[3] + s0B[3]);
                ls[0] += p0 + p1;
                ls[1] += p2 + p3;
                int col = nt * 8 + 2 * c;
                *(uint2*)&Qp[(wr + g) * AST + col]     = make_uint2(f2tf32(p0), f2tf32(p1));
                *(uint2*)&Qp[(wr + g + 8) * AST + col] = make_uint2(f2tf32(p2), f2tf32(p3));
            }
            {
                float p0 = ex2f(s1A[0] + s1B[0]);
                float p1 = ex2f(s1A[1] + s1B[1]);
                float p2 = ex2f(s1A[2] + s1B[2]);
                float p3 = ex2f(s1A[3] + s1B[3]);
                ls[2] += p0 + p1;
                ls[3] += p2 + p3;
                int rb = wr + 16;
                int col = nt * 8 + 2 * c;
                *(uint2*)&Qp[(rb + g) * AST + col]     = make_uint2(f2tf32(p0), f2tf32(p1));
                *(uint2*)&Qp[(rb + g + 8) * AST + col] = make_uint2(f2tf32(p2), f2tf32(p3));
            }
            __syncwarp();  // cross-lane visibility of P(nt) before PV(nt)
        }
        PV_STEP(7);  // drain last step

        __syncthreads();  // all reads of buf[cur] done before next prefetch
    }

    // Row sums across the 4-lane quad; write l and O for both m-tiles.
#pragma unroll
    for (int i = 0; i < 4; i++) {
        ls[i] += __shfl_xor_sync(0xffffffffu, ls[i], 1);
        ls[i] += __shfl_xor_sync(0xffffffffu, ls[i], 2);
    }
    if (c == 0) {
#pragma unroll
        for (int mt = 0; mt < 2; mt++) {
            lp[(size_t)h * N_TOK + q0 + wr + mt * 16 + g]     = ls[mt * 2];
            lp[(size_t)h * N_TOK + q0 + wr + mt * 16 + g + 8] = ls[mt * 2 + 1];
        }
    }

#pragma unroll
    for (int mt = 0; mt < 2; mt++) {
        int rb = q0 + wr + mt * 16;
#pragma unroll
        for (int nt = 0; nt < 8; nt++) {
            int col = h * D_K + nt * 8 + 2 * c;
            *(float2*)&op[(size_t)(rb + g) * D_MODEL + col] =
                make_float2(o[mt][nt][0], o[mt][nt][1]);
            *(float2*)&op[(size_t)(rb + g + 8) * D_MODEL + col] =
                make_float2(o[mt][nt][2], o[mt][nt][3]);
        }
    }
}

// ---------------------------------------------------------------------------
// Combine: attn = tf32(sum_sp O_sp / sum_sp l_sp)
// ---------------------------------------------------------------------------
__global__ void combine_kernel(const float* __restrict__ opart,
                               const float* __restrict__ lpart,
                               float* __restrict__ out)
{
    int i = blockIdx.x * blockDim.x + threadIdx.x;   // float4 index
    if (i >= N_TOK * D_MODEL / 4) return;
    int r  = i / (D_MODEL / 4);
    int c4 = (i % (D_MODEL / 4)) * 4;
    int h  = c4 >> 6;
    float l = 0.0f;
    float4 a = make_float4(0.0f, 0.0f, 0.0f, 0.0f);
#pragma unroll
    for (int sp = 0; sp < KV_SPLIT; sp++) {
        l += lpart[(size_t)sp * N_HEADS * N_TOK + (size_t)h * N_TOK + r];
        float4 t = ((const float4*)(opart + (size_t)sp * N_TOK * D_MODEL))[i];
        a.x += t.x; a.y += t.y; a.z += t.z; a.w += t.w;
    }
    float inv = 1.0f / l;
    float4 o;
    o.x = f2tf32f(a.x * inv); o.y = f2tf32f(a.y * inv);
    o.z = f2tf32f(a.z * inv); o.w = f2tf32f(a.w * inv);
    ((float4*)out)[i] = o;
}

// ---------------------------------------------------------------------------
// Launch
// ---------------------------------------------------------------------------
extern "C" void kernel_launch(void* const* d_in, const int* in_sizes, int n_in,
                              void* d_out, int out_size)
{
    const float* Q  = (const float*)d_in[0];
    const float* K  = (const float*)d_in[1];
    const float* V  = (const float*)d_in[2];
    const float* Wq = (const float*)d_in[3];
    const float* bq = (const float*)d_in[4];
    const float* Wk = (const float*)d_in[5];
    const float* bk = (const float*)d_in[6];
    const float* Wv = (const float*)d_in[7];
    const float* bv = (const float*)d_in[8];
    const float* Wo = (const float*)d_in[9];
    const float* bo = (const float*)d_in[10];
    float* out = (float*)d_out;

    float *qb, *kb, *vb, *ab, *xc, *wc, *op, *lp;
    cudaGetSymbolAddress((void**)&qb, g_q);
    cudaGetSymbolAddress((void**)&kb, g_k);
    cudaGetSymbolAddress((void**)&vb, g_v);
    cudaGetSymbolAddress((void**)&ab, g_attn);
    cudaGetSymbolAddress((void**)&xc, g_xc);
    cudaGetSymbolAddress((void**)&wc, g_wc);
    cudaGetSymbolAddress((void**)&op, g_op);
    cudaGetSymbolAddress((void**)&lp, g_lp);

    float* xc0 = xc;
    float* xc1 = xc + (size_t)N_TOK * D_MODEL;
    float* xc2 = xc + 2 * (size_t)N_TOK * D_MODEL;
    float* wc0 = wc;
    float* wc1 = wc + (size_t)D_MODEL * D_MODEL;
    float* wc2 = wc + 2 * (size_t)D_MODEL * D_MODEL;
    float* wc3 = wc + 3 * (size_t)D_MODEL * D_MODEL;

    // Idempotent, capture-safe (not stream ops).
    cudaFuncSetAttribute(attn_tc_kernel,
                         cudaFuncAttributeMaxDynamicSharedMemorySize, ATT_SMEM_BYTES);
    cudaFuncSetAttribute(qkv_gemm_kernel,
                         cudaFuncAttributeMaxDynamicSharedMemorySize, GEMM_SMEM_BYTES);
    cudaFuncSetAttribute(gemm_o_kernel,
                         cudaFuncAttributeMaxDynamicSharedMemorySize, GEMM_SMEM_BYTES);

    // 1) Pre-convert operands to tf32 (RNA), 2 fused launches.
    dim3 cvtIGrid((NX4 + 255) / 256, 3);
    cvt_inputs_kernel<<<cvtIGrid, 256>>>((const float4*)Q, (const float4*)K,
                                         (const float4*)V, (float4*)xc);
    dim3 cvtWGrid((NW4 + 255) / 256, 4);
    cvt_weights_kernel<<<cvtWGrid, 256>>>((const float4*)Wq, (const float4*)Wk,
                                          (const float4*)Wv, (const float4*)Wo,
                                          (float4*)wc);

    // 2) Fused QKV projections (V written transposed; q scaled by 0.125*log2e).
    dim3 qkvGrid(D_MODEL / GBN, N_TOK / GBM, 3);   // (6, 32, 3)
    qkv_gemm_kernel<<<qkvGrid, 256, GEMM_SMEM_BYTES>>>(
        xc0, xc1, xc2, wc0, wc1, wc2, bq, bk, bv, qb, kb, vb);

    // 3) Split-KV attention (128 threads, 4 warps x 32 rows).
    dim3 attnGrid(N_TOK / 128, N_HEADS, KV_SPLIT); // (32, 12, 4)
    attn_tc_kernel<<<attnGrid, ATT_THREADS, ATT_SMEM_BYTES>>>(qb, kb, vb, op, lp);

    // 4) Combine partials -> g_attn (tf32 bits).
    combine_kernel<<<(NX4 + 255) / 256, 256>>>(op, lp, ab);

    // 5) Output projection.
    dim3 oGrid(D_MODEL / GBN, N_TOK / GBM);        // (6, 32)
    gemm_o_kernel<<<oGrid, 256, GEMM_SMEM_BYTES>>>(ab, wc3, bo, out);
}

// round 15
// speedup vs baseline: 1.1413x; 1.0750x over previous
#include <cuda_runtime.h>
#include <cstdint>

// Problem constants
#define N_TOK   4096
#define D_MODEL 768
#define N_HEADS 12
#define D_K     64
#define KV_SPLIT 4
#define SPLIT_LEN (N_TOK / KV_SPLIT)   // 1024

// ---------------------------------------------------------------------------
// Scratch buffers (float-typed; several hold tf32-rounded bit patterns)
// g_v: TRANSPOSED [h][dk][tok], with token index PERMUTED within each 8-group
//      (sigma: pos p holds orig token 2p (p<4) / 2p-7 (p>=4)) so that PV can
//      consume S-output fragments directly as A operands.
// ---------------------------------------------------------------------------
__device__ float g_q[N_HEADS * N_TOK * D_K];            // tf32 bits, pre-scaled 0.125*log2e
__device__ float g_k[N_HEADS * N_TOK * D_K];            // tf32 bits, [h][tok][dk]
__device__ float g_v[N_HEADS * D_K * N_TOK];            // tf32 bits, see above
__device__ float g_attn[N_TOK * D_MODEL];               // tf32 bits (combine output)
__device__ float g_xc[3][N_TOK * D_MODEL];              // converted inputs Q,K,V
__device__ float g_wc[4][D_MODEL * D_MODEL];            // converted Wq,Wk,Wv,Wo
__device__ float g_op[KV_SPLIT][N_TOK * D_MODEL];       // partial O (unnormalized)
__device__ float g_lp[KV_SPLIT][N_HEADS * N_TOK];       // partial row sums

// ---------------------------------------------------------------------------
// Helpers (baseline sm_80+ PTX only)
// ---------------------------------------------------------------------------
__device__ __forceinline__ uint32_t f2tf32(float f) {
    uint32_t o;
    asm("cvt.rna.tf32.f32 %0, %1;" : "=r"(o) : "f"(f));
    return o;
}
__device__ __forceinline__ float f2tf32f(float f) {
    return __uint_as_float(f2tf32(f));
}
__device__ __forceinline__ float ex2f(float x) {
    float r;
    asm("ex2.approx.f32 %0, %1;" : "=f"(r) : "f"(x));
    return r;
}
__device__ __forceinline__ uint32_t smem_u32(const void* p) {
    uint32_t a;
    asm("{ .reg .u64 t; cvta.to.shared.u64 t, %1; cvt.u32.u64 %0, t; }" : "=r"(a) : "l"(p));
    return a;
}
#define CP_ASYNC16(dst_u32, src) \
    asm volatile("cp.async.cg.shared.global [%0], [%1], 16;" \
                 :: "r"(dst_u32), "l"(src) : "memory")
#define CP_COMMIT() asm volatile("cp.async.commit_group;" ::: "memory")
#define CP_WAIT1()  asm volatile("cp.async.wait_group 1;" ::: "memory")
#define CP_WAIT0()  asm volatile("cp.async.wait_group 0;" ::: "memory")

__device__ __forceinline__ void ldsm_x4(uint32_t& r0, uint32_t& r1,
                                        uint32_t& r2, uint32_t& r3, uint32_t addr) {
    asm volatile("ldmatrix.sync.aligned.m8n8.x4.shared.b16 {%0,%1,%2,%3}, [%4];"
                 : "=r"(r0), "=r"(r1), "=r"(r2), "=r"(r3) : "r"(addr));
}

// D(16x8) += A(16x8) * B(8x8); A row-major, B col-major; fp32 accum.
__device__ __forceinline__ void mma_tf32(float c[4], const uint32_t a[4],
                                         const uint32_t b[2]) {
    asm volatile(
        "mma.sync.aligned.m16n8k8.row.col.f32.tf32.tf32.f32 "
        "{%0,%1,%2,%3}, {%4,%5,%6,%7}, {%8,%9}, {%0,%1,%2,%3};"
        : "+f"(c[0]), "+f"(c[1]), "+f"(c[2]), "+f"(c[3])
        : "r"(a[0]), "r"(a[1]), "r"(a[2]), "r"(a[3]), "r"(b[0]), "r"(b[1]));
}

// ---------------------------------------------------------------------------
// Fused tf32 pre-conversion: inputs (y=0..2) and weights (y=0..3)
// ---------------------------------------------------------------------------
#define NX4 (N_TOK * D_MODEL / 4)
#define NW4 (D_MODEL * D_MODEL / 4)

__global__ void cvt_inputs_kernel(const float4* __restrict__ a,
                                  const float4* __restrict__ b,
                                  const float4* __restrict__ cc,
                                  float4* __restrict__ dst)
{
    int i = blockIdx.x * blockDim.x + threadIdx.x;
    if (i >= NX4) return;
    const float4* src = (blockIdx.y == 0) ? a : (blockIdx.y == 1) ? b : cc;
    float4 t = src[i];
    t.x = f2tf32f(t.x); t.y = f2tf32f(t.y);
    t.z = f2tf32f(t.z); t.w = f2tf32f(t.w);
    dst[(size_t)blockIdx.y * NX4 + i] = t;
}
__global__ void cvt_weights_kernel(const float4* __restrict__ a,
                                   const float4* __restrict__ b,
                                   const float4* __restrict__ cc,
                                   const float4* __restrict__ d,
                                   float4* __restrict__ dst)
{
    int i = blockIdx.x * blockDim.x + threadIdx.x;
    if (i >= NW4) return;
    const float4* src = (blockIdx.y == 0) ? a : (blockIdx.y == 1) ? b
                      : (blockIdx.y == 2) ? cc : d;
    float4 t = src[i];
    t.x = f2tf32f(t.x); t.y = f2tf32f(t.y);
    t.z = f2tf32f(t.z); t.w = f2tf32f(t.w);
    dst[(size_t)blockIdx.y * NW4 + i] = t;
}

// ---------------------------------------------------------------------------
// GEMM mainloop (shared): block 128x128x32, 8 warps (2x4), warp tile 64x32,
// cp.async double-buffered, operands pre-converted tf32 bits (no cvt in loop).
// ---------------------------------------------------------------------------
#define GBM 128
#define GBN 128
#define GBK 32
#define GST 36
#define GEMM_SMEM_BYTES (2 * 2 * GBM * GST * 4)
#define GEMM_NIT (D_MODEL / GBK)   // 24

#define GEMM_PREFETCH(as_, bs_, Xp_, Wp_, k0_) \
    do { \
        for (int i_ = tid; i_ < 1024; i_ += 256) { \
            int r_ = i_ >> 3, c4_ = (i_ & 7) * 4; \
            CP_ASYNC16((as_) + (r_ * GST + c4_) * 4, (Xp_) + (size_t)r_ * D_MODEL + (k0_) + c4_); \
            CP_ASYNC16((bs_) + (r_ * GST + c4_) * 4, (Wp_) + (size_t)r_ * D_MODEL + (k0_) + c4_); \
        } \
        CP_COMMIT(); \
    } while (0)

#define GEMM_MAINLOOP(Xp_, Wp_) \
    { \
        uint32_t as0 = sbase, bs0 = sbase + GBM * GST * 4; \
        GEMM_PREFETCH(as0, bs0, Xp_, Wp_, 0); \
    } \
    for (int it = 0; it < GEMM_NIT; ++it) { \
        const int cur = it & 1; \
        if (it + 1 < GEMM_NIT) { \
            uint32_t as_ = sbase + (uint32_t)(cur ^ 1) * 2 * GBM * GST * 4; \
            uint32_t bs_ = as_ + GBM * GST * 4; \
            GEMM_PREFETCH(as_, bs_, Xp_, Wp_, (it + 1) * GBK); \
            CP_WAIT1(); \
        } else { \
            CP_WAIT0(); \
        } \
        __syncthreads(); \
        const uint32_t* As = gsh + (size_t)cur * 2 * GBM * GST; \
        const uint32_t* Bs = As + GBM * GST; \
        _Pragma("unroll") \
        for (int s = 0; s < 4; s++) { \
            const int c0 = s * 8; \
            uint32_t a[4][4], b[4][2]; \
            _Pragma("unroll") \
            for (int mt = 0; mt < 4; mt++) { \
                int r = wm * 64 + mt * 16 + g; \
                a[mt][0] = As[r * GST + c0 + c]; \
                a[mt][1] = As[(r + 8) * GST + c0 + c]; \
                a[mt][2] = As[r * GST + c0 + c + 4]; \
                a[mt][3] = As[(r + 8) * GST + c0 + c + 4]; \
            } \
            _Pragma("unroll") \
            for (int nt = 0; nt < 4; nt++) { \
                int n = wn * 32 + nt * 8 + g; \
                b[nt][0] = Bs[n * GST + c0 + c]; \
                b[nt][1] = Bs[n * GST + c0 + c + 4]; \
            } \
            _Pragma("unroll") \
            for (int mt = 0; mt < 4; mt++) \
                _Pragma("unroll") \
                for (int nt = 0; nt < 4; nt++) \
                    mma_tf32(acc[mt][nt], a[mt], b[nt]); \
        } \
        __syncthreads(); \
    }

// ---------------------------------------------------------------------------
// Fused QKV projection. Grid (6, 32, 3). z=0: q (scaled by 0.125*log2e,
// [h][tok][dk]), z=1: k ([h][tok][dk]), z=2: v TRANSPOSED [h][dk][tok'] with
// tok' sigma-permuted within 8-groups (see g_v comment).
// ---------------------------------------------------------------------------
#define QSCALE 0.18033688011112042f   // 0.125 * log2(e)

__global__ void __launch_bounds__(256) qkv_gemm_kernel(
    const float* __restrict__ x0, const float* __restrict__ x1, const float* __restrict__ x2,
    const float* __restrict__ w0, const float* __restrict__ w1, const float* __restrict__ w2,
    const float* __restrict__ bq_, const float* __restrict__ bk_, const float* __restrict__ bv_,
    float* __restrict__ o0, float* __restrict__ o1, float* __restrict__ o2)
{
    extern __shared__ uint32_t gsh[];
    const int tid  = threadIdx.x;
    const int wid  = tid >> 5;
    const int lane = tid & 31;
    const int g    = lane >> 2;
    const int c    = lane & 3;
    const int wm   = wid >> 2;
    const int wn   = wid & 3;
    const int m0   = blockIdx.y * GBM;
    const int n0   = blockIdx.x * GBN;
    const int z    = blockIdx.z;

    const float* X    = (z == 0) ? x0 : (z == 1) ? x1 : x2;
    const float* W    = (z == 0) ? w0 : (z == 1) ? w1 : w2;
    const float* bias = (z == 0) ? bq_ : (z == 1) ? bk_ : bv_;
    const float scale = (z == 0) ? QSCALE : 1.0f;

    const uint32_t sbase = smem_u32(gsh);
    const float* Xp = X + (size_t)m0 * D_MODEL;
    const float* Wp = W + (size_t)n0 * D_MODEL;

    float acc[4][4][4];
#pragma unroll
    for (int i = 0; i < 4; i++)
#pragma unroll
        for (int j = 0; j < 4; j++)
#pragma unroll
            for (int f = 0; f < 4; f++) acc[i][j][f] = 0.0f;

    GEMM_MAINLOOP(Xp, Wp)

#pragma unroll
    for (int nt = 0; nt < 4; nt++) {
        int col = n0 + wn * 32 + nt * 8 + 2 * c;
        float b0 = bias[col], b1 = bias[col + 1];
        int h = col >> 6, t = col & 63;
#pragma unroll
        for (int mt = 0; mt < 4; mt++) {
            int row = m0 + wm * 64 + mt * 16 + g;
            float v00 = f2tf32f((acc[mt][nt][0] + b0) * scale);
            float v01 = f2tf32f((acc[mt][nt][1] + b1) * scale);
            float v10 = f2tf32f((acc[mt][nt][2] + b0) * scale);
            float v11 = f2tf32f((acc[mt][nt][3] + b1) * scale);
            if (z == 2) {
                // transposed + sigma^-1 permute token within 8-group:
                // orig token row (r8=g) stored at position: even g -> g/2,
                // odd g -> 4 + g/2.
                int rp = (g & 1) ? (4 + (g >> 1)) : (g >> 1);
                int prow = (row & ~7) | rp;
                float* vp = o2;
                vp[((size_t)h * D_K + t)     * N_TOK + prow]     = v00;
                vp[((size_t)h * D_K + t + 1) * N_TOK + prow]     = v01;
                vp[((size_t)h * D_K + t)     * N_TOK + prow + 8] = v10;
                vp[((size_t)h * D_K + t + 1) * N_TOK + prow + 8] = v11;
            } else {
                float* outp = (z == 0) ? o0 : o1;
                *(float2*)&outp[((size_t)h * N_TOK + row) * D_K + t]     = make_float2(v00, v01);
                *(float2*)&outp[((size_t)h * N_TOK + row + 8) * D_K + t] = make_float2(v10, v11);
            }
        }
    }
}

// ---------------------------------------------------------------------------
// Output projection
// ---------------------------------------------------------------------------
__global__ void __launch_bounds__(256) gemm_o_kernel(
    const float* __restrict__ X, const float* __restrict__ W,
    const float* __restrict__ bias, float* __restrict__ out)
{
    extern __shared__ uint32_t gsh[];
    const int tid  = threadIdx.x;
    const int wid  = tid >> 5;
    const int lane = tid & 31;
    const int g    = lane >> 2;
    const int c    = lane & 3;
    const int wm   = wid >> 2;
    const int wn   = wid & 3;
    const int m0   = blockIdx.y * GBM;
    const int n0   = blockIdx.x * GBN;

    const uint32_t sbase = smem_u32(gsh);
    const float* Xp = X + (size_t)m0 * D_MODEL;
    const float* Wp = W + (size_t)n0 * D_MODEL;

    float acc[4][4][4];
#pragma unroll
    for (int i = 0; i < 4; i++)
#pragma unroll
        for (int j = 0; j < 4; j++)
#pragma unroll
            for (int f = 0; f < 4; f++) acc[i][j][f] = 0.0f;

    GEMM_MAINLOOP(Xp, Wp)

#pragma unroll
    for (int nt = 0; nt < 4; nt++) {
        int col = n0 + wn * 32 + nt * 8 + 2 * c;
        float b0 = bias[col], b1 = bias[col + 1];
#pragma unroll
        for (int mt = 0; mt < 4; mt++) {
            int row = m0 + wm * 64 + mt * 16 + g;
            *(float2*)&out[(size_t)row * D_MODEL + col] =
                make_float2(acc[mt][nt][0] + b0, acc[mt][nt][1] + b1);
            *(float2*)&out[(size_t)(row + 8) * D_MODEL + col] =
                make_float2(acc[mt][nt][2] + b0, acc[mt][nt][3] + b1);
        }
    }
}

// ---------------------------------------------------------------------------
// Flash attention, split-KV, ldmatrix loads, 2 m-tiles/warp,
// REGISTER-LEVEL S->PV handoff: exp(S) fragments ARE the PV A-operand
// (V tokens sigma-permuted in gmem to match). No P smem traffic at all.
// Grid (32, 12, KV_SPLIT), 128 threads (4 warps x 32 q-rows). kv tiles of 64.
// smem: Qp[128*68] (Q prologue only), Ks 2x[64*68], Vt 2x[64*68].
// ---------------------------------------------------------------------------
#define AST 68
#define VST2 68
#define ATT_QW   (128 * AST)
#define ATT_KW   (64 * AST)
#define ATT_VW   (64 * VST2)
#define ATT_SMEM_BYTES ((ATT_QW + 2 * ATT_KW + 2 * ATT_VW) * 4)
#define ATT_THREADS 128

__global__ void __launch_bounds__(ATT_THREADS, 2) attn_tc_kernel(
    const float* __restrict__ q, const float* __restrict__ k,
    const float* __restrict__ v, float* __restrict__ opart,
    float* __restrict__ lpart)
{
    extern __shared__ uint32_t sh[];
    uint32_t* Qp  = sh;
    uint32_t* Ksb[2] = { sh + ATT_QW, sh + ATT_QW + ATT_KW };
    uint32_t* Vsb[2] = { sh + ATT_QW + 2 * ATT_KW, sh + ATT_QW + 2 * ATT_KW + ATT_VW };

    const int tid  = threadIdx.x;
    const int wid  = tid >> 5;
    const int lane = tid & 31;
    const int g    = lane >> 2;
    const int c    = lane & 3;
    const int wr   = wid * 32;         // this warp's 32-row block
    const int h    = blockIdx.y;
    const int q0   = blockIdx.x * 128;
    const int sp   = blockIdx.z;

    float* op = opart + (size_t)sp * N_TOK * D_MODEL;
    float* lp = lpart + (size_t)sp * N_HEADS * N_TOK;

    const float* kh = k + ((size_t)h * N_TOK + sp * SPLIT_LEN) * D_K;   // [tok][dk]
    const float* vh = v + (size_t)h * D_K * N_TOK + sp * SPLIT_LEN;     // [dk][tok']

    // ldmatrix per-lane address components (bytes)
    const int m_ = lane >> 3, r_ = lane & 7;
    const uint32_t KsA0 = smem_u32(Ksb[0]), KsA1 = smem_u32(Ksb[1]);
    const uint32_t VsA0 = smem_u32(Vsb[0]), VsA1 = smem_u32(Vsb[1]);
    const uint32_t kOff = (uint32_t)(r_ * AST + 4 * m_) * 4;
    const uint32_t vOff = (uint32_t)(((m_ >> 1) * 8 + r_) * VST2 + 4 * (m_ & 1)) * 4;

    // Prefetch kv tile 0.
    {
        uint32_t ks = KsA0, vs = VsA0;
#pragma unroll
        for (int i = tid; i < 1024; i += ATT_THREADS) {
            int r = i >> 4, c4 = (i & 15) * 4;
            CP_ASYNC16(ks + (r * AST + c4) * 4, kh + (size_t)r * D_K + c4);
            CP_ASYNC16(vs + (r * VST2 + c4) * 4, vh + (size_t)r * N_TOK + c4);
        }
        CP_COMMIT();
    }

    // Q tile: already scaled + tf32 bits -> plain copy into smem (prologue only).
    const float* qh = q + ((size_t)h * N_TOK + q0) * D_K;
#pragma unroll
    for (int i = tid; i < 2048; i += ATT_THREADS) {
        int r = i >> 4, c4 = (i & 15) * 4;
        uint4 t = *(const uint4*)(qh + (size_t)r * D_K + c4);
        *(uint4*)&Qp[r * AST + c4] = t;
    }
    __syncthreads();

    // Persistent Q fragments: 2 m-tiles x 8 k-steps.
    uint32_t qa[2][8][4];
#pragma unroll
    for (int mt = 0; mt < 2; mt++) {
        int rb = wr + mt * 16;
#pragma unroll
        for (int s = 0; s < 8; s++) {
            int c0 = s * 8;
            qa[mt][s][0] = Qp[(rb + g) * AST + c0 + c];
            qa[mt][s][1] = Qp[(rb + g + 8) * AST + c0 + c];
            qa[mt][s][2] = Qp[(rb + g) * AST + c0 + c + 4];
            qa[mt][s][3] = Qp[(rb + g + 8) * AST + c0 + c + 4];
        }
    }

    float o[2][8][4];
#pragma unroll
    for (int mt = 0; mt < 2; mt++)
#pragma unroll
        for (int nt = 0; nt < 8; nt++)
#pragma unroll
            for (int f = 0; f < 4; f++) o[mt][nt][f] = 0.0f;
    float ls[4] = {0.0f, 0.0f, 0.0f, 0.0f};   // [mt*2 + (0:row g,1:row g+8)]

    const int NIT = SPLIT_LEN / 64;  // 16
    for (int it = 0; it < NIT; ++it) {
        const int cur = it & 1;
        if (it + 1 < NIT) {
            const int kt = (it + 1) * 64;
            uint32_t ks = cur ? KsA0 : KsA1;
            uint32_t vs = cur ? VsA0 : VsA1;
#pragma unroll
            for (int i = tid; i < 1024; i += ATT_THREADS) {
                int r = i >> 4, c4 = (i & 15) * 4;
                CP_ASYNC16(ks + (r * AST + c4) * 4, kh + (size_t)(kt + r) * D_K + c4);
                CP_ASYNC16(vs + (r * VST2 + c4) * 4, vh + (size_t)r * N_TOK + kt + c4);
            }
            CP_COMMIT();
            CP_WAIT1();
        } else {
            CP_WAIT0();
        }
        __syncthreads();

        const uint32_t KsA = cur ? KsA1 : KsA0;
        const uint32_t VsA = cur ? VsA1 : VsA0;

        // Per nt: S MMAs -> V ldsm -> exp -> PV MMAs (P stays in registers).
#pragma unroll
        for (int nt = 0; nt < 8; nt++) {
            uint32_t bb[8][2];
            const uint32_t kb = KsA + kOff + (uint32_t)nt * (8 * AST * 4);
#pragma unroll
            for (int j = 0; j < 4; j++)
                ldsm_x4(bb[2 * j][0], bb[2 * j][1], bb[2 * j + 1][0], bb[2 * j + 1][1],
                        kb + (uint32_t)j * 64);

            float s0A[4] = {0.0f, 0.0f, 0.0f, 0.0f};
            float s0B[4] = {0.0f, 0.0f, 0.0f, 0.0f};
            float s1A[4] = {0.0f, 0.0f, 0.0f, 0.0f};
            float s1B[4] = {0.0f, 0.0f, 0.0f, 0.0f};
#pragma unroll
            for (int s = 0; s < 4; s++) {
                mma_tf32(s0A, qa[0][s], bb[s]);
                mma_tf32(s0B, qa[0][s + 4], bb[s + 4]);
                mma_tf32(s1A, qa[1][s], bb[s]);
                mma_tf32(s1B, qa[1][s + 4], bb[s + 4]);
            }

            // V B-fragments for this kv chunk (independent of S results).
            uint32_t bv[4][4];
            const uint32_t vb = VsA + vOff + (uint32_t)nt * 32;
#pragma unroll
            for (int j = 0; j < 4; j++)
                ldsm_x4(bv[j][0], bv[j][1], bv[j][2], bv[j][3],
                        vb + (uint32_t)j * (16 * VST2 * 4));

            // exp2 + row sums + pack P fragments (register reorder only:
            // A-frag = {p0, p2, p1, p3}; V token permutation compensates).
            uint32_t pa[2][4];
            {
                float p0 = ex2f(s0A[0] + s0B[0]);
                float p1 = ex2f(s0A[1] + s0B[1]);
                float p2 = ex2f(s0A[2] + s0B[2]);
                float p3 = ex2f(s0A[3] + s0B[3]);
                ls[0] += p0 + p1;
                ls[1] += p2 + p3;
                pa[0][0] = f2tf32(p0); pa[0][1] = f2tf32(p2);
                pa[0][2] = f2tf32(p1); pa[0][3] = f2tf32(p3);
            }
            {
                float p0 = ex2f(s1A[0] + s1B[0]);
                float p1 = ex2f(s1A[1] + s1B[1]);
                float p2 = ex2f(s1A[2] + s1B[2]);
                float p3 = ex2f(s1A[3] + s1B[3]);
                ls[2] += p0 + p1;
                ls[3] += p2 + p3;
                pa[1][0] = f2tf32(p0); pa[1][1] = f2tf32(p2);
                pa[1][2] = f2tf32(p1); pa[1][3] = f2tf32(p3);
            }

            // PV: O[:, dk] += P(nt) . V(nt chunk)
#pragma unroll
            for (int j = 0; j < 4; j++) {
                uint32_t bA[2] = {bv[j][0], bv[j][1]};
                uint32_t bB[2] = {bv[j][2], bv[j][3]};
#pragma unroll
                for (int mt = 0; mt < 2; mt++) {
                    mma_tf32(o[mt][2 * j], pa[mt], bA);
                    mma_tf32(o[mt][2 * j + 1], pa[mt], bB);
                }
            }
        }

        __syncthreads();  // all reads of buf[cur] done before next prefetch
    }

    // Row sums across the 4-lane quad; write l and O for both m-tiles.
#pragma unroll
    for (int i = 0; i < 4; i++) {
        ls[i] += __shfl_xor_sync(0xffffffffu, ls[i], 1);
        ls[i] += __shfl_xor_sync(0xffffffffu, ls[i], 2);
    }
    if (c == 0) {
#pragma unroll
        for (int mt = 0; mt < 2; mt++) {
            lp[(size_t)h * N_TOK + q0 + wr + mt * 16 + g]     = ls[mt * 2];
            lp[(size_t)h * N_TOK + q0 + wr + mt * 16 + g + 8] = ls[mt * 2 + 1];
        }
    }

#pragma unroll
    for (int mt = 0; mt < 2; mt++) {
        int rb = q0 + wr + mt * 16;
#pragma unroll
        for (int nt = 0; nt < 8; nt++) {
            int col = h * D_K + nt * 8 + 2 * c;
            *(float2*)&op[(size_t)(rb + g) * D_MODEL + col] =
                make_float2(o[mt][nt][0], o[mt][nt][1]);
            *(float2*)&op[(size_t)(rb + g + 8) * D_MODEL + col] =
                make_float2(o[mt][nt][2], o[mt][nt][3]);
        }
    }
}

// ---------------------------------------------------------------------------
// Combine: attn = tf32(sum_sp O_sp / sum_sp l_sp)
// ---------------------------------------------------------------------------
__global__ void combine_kernel(const float* __restrict__ opart,
                               const float* __restrict__ lpart,
                               float* __restrict__ out)
{
    int i = blockIdx.x * blockDim.x + threadIdx.x;   // float4 index
    if (i >= N_TOK * D_MODEL / 4) return;
    int r  = i / (D_MODEL / 4);
    int c4 = (i % (D_MODEL / 4)) * 4;
    int h  = c4 >> 6;
    float l = 0.0f;
    float4 a = make_float4(0.0f, 0.0f, 0.0f, 0.0f);
#pragma unroll
    for (int sp = 0; sp < KV_SPLIT; sp++) {
        l += lpart[(size_t)sp * N_HEADS * N_TOK + (size_t)h * N_TOK + r];
        float4 t = ((const float4*)(opart + (size_t)sp * N_TOK * D_MODEL))[i];
        a.x += t.x; a.y += t.y; a.z += t.z; a.w += t.w;
    }
    float inv = 1.0f / l;
    float4 o;
    o.x = f2tf32f(a.x * inv); o.y = f2tf32f(a.y * inv);
    o.z = f2tf32f(a.z * inv); o.w = f2tf32f(a.w * inv);
    ((float4*)out)[i] = o;
}

// ---------------------------------------------------------------------------
// Launch
// ---------------------------------------------------------------------------
extern "C" void kernel_launch(void* const* d_in, const int* in_sizes, int n_in,
                              void* d_out, int out_size)
{
    const float* Q  = (const float*)d_in[0];
    const float* K  = (const float*)d_in[1];
    const float* V  = (const float*)d_in[2];
    const float* Wq = (const float*)d_in[3];
    const float* bq = (const float*)d_in[4];
    const float* Wk = (const float*)d_in[5];
    const float* bk = (const float*)d_in[6];
    const float* Wv = (const float*)d_in[7];
    const float* bv = (const float*)d_in[8];
    const float* Wo = (const float*)d_in[9];
    const float* bo = (const float*)d_in[10];
    float* out = (float*)d_out;

    float *qb, *kb, *vb, *ab, *xc, *wc, *op, *lp;
    cudaGetSymbolAddress((void**)&qb, g_q);
    cudaGetSymbolAddress((void**)&kb, g_k);
    cudaGetSymbolAddress((void**)&vb, g_v);
    cudaGetSymbolAddress((void**)&ab, g_attn);
    cudaGetSymbolAddress((void**)&xc, g_xc);
    cudaGetSymbolAddress((void**)&wc, g_wc);
    cudaGetSymbolAddress((void**)&op, g_op);
    cudaGetSymbolAddress((void**)&lp, g_lp);

    float* xc0 = xc;
    float* xc1 = xc + (size_t)N_TOK * D_MODEL;
    float* xc2 = xc + 2 * (size_t)N_TOK * D_MODEL;
    float* wc0 = wc;
    float* wc1 = wc + (size_t)D_MODEL * D_MODEL;
    float* wc2 = wc + 2 * (size_t)D_MODEL * D_MODEL;
    float* wc3 = wc + 3 * (size_t)D_MODEL * D_MODEL;

    // Idempotent, capture-safe (not stream ops).
    cudaFuncSetAttribute(attn_tc_kernel,
                         cudaFuncAttributeMaxDynamicSharedMemorySize, ATT_SMEM_BYTES);
    cudaFuncSetAttribute(qkv_gemm_kernel,
                         cudaFuncAttributeMaxDynamicSharedMemorySize, GEMM_SMEM_BYTES);
    cudaFuncSetAttribute(gemm_o_kernel,
                         cudaFuncAttributeMaxDynamicSharedMemorySize, GEMM_SMEM_BYTES);

    // 1) Pre-convert operands to tf32 (RNA), 2 fused launches.
    dim3 cvtIGrid((NX4 + 255) / 256, 3);
    cvt_inputs_kernel<<<cvtIGrid, 256>>>((const float4*)Q, (const float4*)K,
                                         (const float4*)V, (float4*)xc);
    dim3 cvtWGrid((NW4 + 255) / 256, 4);
    cvt_weights_kernel<<<cvtWGrid, 256>>>((const float4*)Wq, (const float4*)Wk,
                                          (const float4*)Wv, (const float4*)Wo,
                                          (float4*)wc);

    // 2) Fused QKV projections (V transposed + sigma-permuted; q pre-scaled).
    dim3 qkvGrid(D_MODEL / GBN, N_TOK / GBM, 3);   // (6, 32, 3)
    qkv_gemm_kernel<<<qkvGrid, 256, GEMM_SMEM_BYTES>>>(
        xc0, xc1, xc2, wc0, wc1, wc2, bq, bk, bv, qb, kb, vb);

    // 3) Split-KV attention (128 threads, 4 warps x 32 rows).
    dim3 attnGrid(N_TOK / 128, N_HEADS, KV_SPLIT); // (32, 12, 4)
    attn_tc_kernel<<<attnGrid, ATT_THREADS, ATT_SMEM_BYTES>>>(qb, kb, vb, op, lp);

    // 4) Combine partials -> g_attn (tf32 bits).
    combine_kernel<<<(NX4 + 255) / 256, 256>>>(op, lp, ab);

    // 5) Output projection.
    dim3 oGrid(D_MODEL / GBN, N_TOK / GBM);        // (6, 32)
    gemm_o_kernel<<<oGrid, 256, GEMM_SMEM_BYTES>>>(ab, wc3, bo, out);
}

// round 16
// speedup vs baseline: 1.1457x; 1.0038x over previous
#include <cuda_runtime.h>
#include <cstdint>

// Problem constants
#define N_TOK   4096
#define D_MODEL 768
#define N_HEADS 12
#define D_K     64
#define KV_SPLIT 4
#define SPLIT_LEN (N_TOK / KV_SPLIT)   // 1024

// ---------------------------------------------------------------------------
// Scratch buffers (float-typed; several hold tf32-rounded bit patterns)
// g_v: TRANSPOSED [h][dk][tok], token index PERMUTED within each 8-group
//      (sigma: even g -> g/2, odd g -> 4+g/2) so PV consumes exp(S) fragments
//      directly as A operands.
// ---------------------------------------------------------------------------
__device__ float g_q[N_HEADS * N_TOK * D_K];            // tf32 bits, pre-scaled 0.125*log2e
__device__ float g_k[N_HEADS * N_TOK * D_K];            // tf32 bits, [h][tok][dk]
__device__ float g_v[N_HEADS * D_K * N_TOK];            // tf32 bits, see above
__device__ float g_attn[N_TOK * D_MODEL];               // tf32 bits (combine output)
__device__ float g_xc[3][N_TOK * D_MODEL];              // converted inputs Q,K,V
__device__ float g_wc[4][D_MODEL * D_MODEL];            // converted Wq,Wk,Wv,Wo
__device__ float g_op[KV_SPLIT][N_TOK * D_MODEL];       // partial O (unnormalized)
__device__ float g_lp[KV_SPLIT][N_HEADS * N_TOK];       // partial row sums

// ---------------------------------------------------------------------------
// Helpers (baseline sm_80+ PTX only)
// ---------------------------------------------------------------------------
__device__ __forceinline__ uint32_t f2tf32(float f) {
    uint32_t o;
    asm("cvt.rna.tf32.f32 %0, %1;" : "=r"(o) : "f"(f));
    return o;
}
__device__ __forceinline__ float f2tf32f(float f) {
    return __uint_as_float(f2tf32(f));
}
__device__ __forceinline__ float ex2f(float x) {
    float r;
    asm("ex2.approx.f32 %0, %1;" : "=f"(r) : "f"(x));
    return r;
}
__device__ __forceinline__ uint32_t smem_u32(const void* p) {
    uint32_t a;
    asm("{ .reg .u64 t; cvta.to.shared.u64 t, %1; cvt.u32.u64 %0, t; }" : "=r"(a) : "l"(p));
    return a;
}
#define CP_ASYNC16(dst_u32, src) \
    asm volatile("cp.async.cg.shared.global [%0], [%1], 16;" \
                 :: "r"(dst_u32), "l"(src) : "memory")
#define CP_COMMIT() asm volatile("cp.async.commit_group;" ::: "memory")
#define CP_WAIT1()  asm volatile("cp.async.wait_group 1;" ::: "memory")
#define CP_WAIT0()  asm volatile("cp.async.wait_group 0;" ::: "memory")

__device__ __forceinline__ void ldsm_x4(uint32_t& r0, uint32_t& r1,
                                        uint32_t& r2, uint32_t& r3, uint32_t addr) {
    asm volatile("ldmatrix.sync.aligned.m8n8.x4.shared.b16 {%0,%1,%2,%3}, [%4];"
                 : "=r"(r0), "=r"(r1), "=r"(r2), "=r"(r3) : "r"(addr));
}

// D(16x8) += A(16x8) * B(8x8); A row-major, B col-major; fp32 accum.
__device__ __forceinline__ void mma_tf32(float c[4], const uint32_t a[4],
                                         const uint32_t b[2]) {
    asm volatile(
        "mma.sync.aligned.m16n8k8.row.col.f32.tf32.tf32.f32 "
        "{%0,%1,%2,%3}, {%4,%5,%6,%7}, {%8,%9}, {%0,%1,%2,%3};"
        : "+f"(c[0]), "+f"(c[1]), "+f"(c[2]), "+f"(c[3])
        : "r"(a[0]), "r"(a[1]), "r"(a[2]), "r"(a[3]), "r"(b[0]), "r"(b[1]));
}

// ---------------------------------------------------------------------------
// Fused tf32 pre-conversion: inputs (y=0..2) and weights (y=0..3)
// ---------------------------------------------------------------------------
#define NX4 (N_TOK * D_MODEL / 4)
#define NW4 (D_MODEL * D_MODEL / 4)

__global__ void cvt_inputs_kernel(const float4* __restrict__ a,
                                  const float4* __restrict__ b,
                                  const float4* __restrict__ cc,
                                  float4* __restrict__ dst)
{
    int i = blockIdx.x * blockDim.x + threadIdx.x;
    if (i >= NX4) return;
    const float4* src = (blockIdx.y == 0) ? a : (blockIdx.y == 1) ? b : cc;
    float4 t = src[i];
    t.x = f2tf32f(t.x); t.y = f2tf32f(t.y);
    t.z = f2tf32f(t.z); t.w = f2tf32f(t.w);
    dst[(size_t)blockIdx.y * NX4 + i] = t;
}
__global__ void cvt_weights_kernel(const float4* __restrict__ a,
                                   const float4* __restrict__ b,
                                   const float4* __restrict__ cc,
                                   const float4* __restrict__ d,
                                   float4* __restrict__ dst)
{
    int i = blockIdx.x * blockDim.x + threadIdx.x;
    if (i >= NW4) return;
    const float4* src = (blockIdx.y == 0) ? a : (blockIdx.y == 1) ? b
                      : (blockIdx.y == 2) ? cc : d;
    float4 t = src[i];
    t.x = f2tf32f(t.x); t.y = f2tf32f(t.y);
    t.z = f2tf32f(t.z); t.w = f2tf32f(t.w);
    dst[(size_t)blockIdx.y * NW4 + i] = t;
}

// ---------------------------------------------------------------------------
// GEMM mainloop (shared): block 128x128x32, 8 warps (2x4), warp tile 64x32,
// cp.async double-buffered, operands pre-converted tf32 bits (no cvt in loop).
// ---------------------------------------------------------------------------
#define GBM 128
#define GBN 128
#define GBK 32
#define GST 36
#define GEMM_SMEM_BYTES (2 * 2 * GBM * GST * 4)
#define GEMM_NIT (D_MODEL / GBK)   // 24

#define GEMM_PREFETCH(as_, bs_, Xp_, Wp_, k0_) \
    do { \
        for (int i_ = tid; i_ < 1024; i_ += 256) { \
            int r_ = i_ >> 3, c4_ = (i_ & 7) * 4; \
            CP_ASYNC16((as_) + (r_ * GST + c4_) * 4, (Xp_) + (size_t)r_ * D_MODEL + (k0_) + c4_); \
            CP_ASYNC16((bs_) + (r_ * GST + c4_) * 4, (Wp_) + (size_t)r_ * D_MODEL + (k0_) + c4_); \
        } \
        CP_COMMIT(); \
    } while (0)

#define GEMM_MAINLOOP(Xp_, Wp_) \
    { \
        uint32_t as0 = sbase, bs0 = sbase + GBM * GST * 4; \
        GEMM_PREFETCH(as0, bs0, Xp_, Wp_, 0); \
    } \
    for (int it = 0; it < GEMM_NIT; ++it) { \
        const int cur = it & 1; \
        if (it + 1 < GEMM_NIT) { \
            uint32_t as_ = sbase + (uint32_t)(cur ^ 1) * 2 * GBM * GST * 4; \
            uint32_t bs_ = as_ + GBM * GST * 4; \
            GEMM_PREFETCH(as_, bs_, Xp_, Wp_, (it + 1) * GBK); \
            CP_WAIT1(); \
        } else { \
            CP_WAIT0(); \
        } \
        __syncthreads(); \
        const uint32_t* As = gsh + (size_t)cur * 2 * GBM * GST; \
        const uint32_t* Bs = As + GBM * GST; \
        _Pragma("unroll") \
        for (int s = 0; s < 4; s++) { \
            const int c0 = s * 8; \
            uint32_t a[4][4], b[4][2]; \
            _Pragma("unroll") \
            for (int mt = 0; mt < 4; mt++) { \
                int r = wm * 64 + mt * 16 + g; \
                a[mt][0] = As[r * GST + c0 + c]; \
                a[mt][1] = As[(r + 8) * GST + c0 + c]; \
                a[mt][2] = As[r * GST + c0 + c + 4]; \
                a[mt][3] = As[(r + 8) * GST + c0 + c + 4]; \
            } \
            _Pragma("unroll") \
            for (int nt = 0; nt < 4; nt++) { \
                int n = wn * 32 + nt * 8 + g; \
                b[nt][0] = Bs[n * GST + c0 + c]; \
                b[nt][1] = Bs[n * GST + c0 + c + 4]; \
            } \
            _Pragma("unroll") \
            for (int mt = 0; mt < 4; mt++) \
                _Pragma("unroll") \
                for (int nt = 0; nt < 4; nt++) \
                    mma_tf32(acc[mt][nt], a[mt], b[nt]); \
        } \
        __syncthreads(); \
    }

// ---------------------------------------------------------------------------
// Fused QKV projection. Grid (6, 32, 3). z=0: q (scaled by 0.125*log2e,
// [h][tok][dk]), z=1: k ([h][tok][dk]), z=2: v TRANSPOSED [h][dk][tok'] with
// tok' sigma-permuted within 8-groups (see g_v comment).
// ---------------------------------------------------------------------------
#define QSCALE 0.18033688011112042f   // 0.125 * log2(e)

__global__ void __launch_bounds__(256) qkv_gemm_kernel(
    const float* __restrict__ x0, const float* __restrict__ x1, const float* __restrict__ x2,
    const float* __restrict__ w0, const float* __restrict__ w1, const float* __restrict__ w2,
    const float* __restrict__ bq_, const float* __restrict__ bk_, const float* __restrict__ bv_,
    float* __restrict__ o0, float* __restrict__ o1, float* __restrict__ o2)
{
    extern __shared__ uint32_t gsh[];
    const int tid  = threadIdx.x;
    const int wid  = tid >> 5;
    const int lane = tid & 31;
    const int g    = lane >> 2;
    const int c    = lane & 3;
    const int wm   = wid >> 2;
    const int wn   = wid & 3;
    const int m0   = blockIdx.y * GBM;
    const int n0   = blockIdx.x * GBN;
    const int z    = blockIdx.z;

    const float* X    = (z == 0) ? x0 : (z == 1) ? x1 : x2;
    const float* W    = (z == 0) ? w0 : (z == 1) ? w1 : w2;
    const float* bias = (z == 0) ? bq_ : (z == 1) ? bk_ : bv_;
    const float scale = (z == 0) ? QSCALE : 1.0f;

    const uint32_t sbase = smem_u32(gsh);
    const float* Xp = X + (size_t)m0 * D_MODEL;
    const float* Wp = W + (size_t)n0 * D_MODEL;

    float acc[4][4][4];
#pragma unroll
    for (int i = 0; i < 4; i++)
#pragma unroll
        for (int j = 0; j < 4; j++)
#pragma unroll
            for (int f = 0; f < 4; f++) acc[i][j][f] = 0.0f;

    GEMM_MAINLOOP(Xp, Wp)

#pragma unroll
    for (int nt = 0; nt < 4; nt++) {
        int col = n0 + wn * 32 + nt * 8 + 2 * c;
        float b0 = bias[col], b1 = bias[col + 1];
        int h = col >> 6, t = col & 63;
#pragma unroll
        for (int mt = 0; mt < 4; mt++) {
            int row = m0 + wm * 64 + mt * 16 + g;
            float v00 = f2tf32f((acc[mt][nt][0] + b0) * scale);
            float v01 = f2tf32f((acc[mt][nt][1] + b1) * scale);
            float v10 = f2tf32f((acc[mt][nt][2] + b0) * scale);
            float v11 = f2tf32f((acc[mt][nt][3] + b1) * scale);
            if (z == 2) {
                // transposed + sigma^-1 permute token within 8-group.
                int rp = (g & 1) ? (4 + (g >> 1)) : (g >> 1);
                int prow = (row & ~7) | rp;
                float* vp = o2;
                vp[((size_t)h * D_K + t)     * N_TOK + prow]     = v00;
                vp[((size_t)h * D_K + t + 1) * N_TOK + prow]     = v01;
                vp[((size_t)h * D_K + t)     * N_TOK + prow + 8] = v10;
                vp[((size_t)h * D_K + t + 1) * N_TOK + prow + 8] = v11;
            } else {
                float* outp = (z == 0) ? o0 : o1;
                *(float2*)&outp[((size_t)h * N_TOK + row) * D_K + t]     = make_float2(v00, v01);
                *(float2*)&outp[((size_t)h * N_TOK + row + 8) * D_K + t] = make_float2(v10, v11);
            }
        }
    }
}

// ---------------------------------------------------------------------------
// Output projection
// ---------------------------------------------------------------------------
__global__ void __launch_bounds__(256) gemm_o_kernel(
    const float* __restrict__ X, const float* __restrict__ W,
    const float* __restrict__ bias, float* __restrict__ out)
{
    extern __shared__ uint32_t gsh[];
    const int tid  = threadIdx.x;
    const int wid  = tid >> 5;
    const int lane = tid & 31;
    const int g    = lane >> 2;
    const int c    = lane & 3;
    const int wm   = wid >> 2;
    const int wn   = wid & 3;
    const int m0   = blockIdx.y * GBM;
    const int n0   = blockIdx.x * GBN;

    const uint32_t sbase = smem_u32(gsh);
    const float* Xp = X + (size_t)m0 * D_MODEL;
    const float* Wp = W + (size_t)n0 * D_MODEL;

    float acc[4][4][4];
#pragma unroll
    for (int i = 0; i < 4; i++)
#pragma unroll
        for (int j = 0; j < 4; j++)
#pragma unroll
            for (int f = 0; f < 4; f++) acc[i][j][f] = 0.0f;

    GEMM_MAINLOOP(Xp, Wp)

#pragma unroll
    for (int nt = 0; nt < 4; nt++) {
        int col = n0 + wn * 32 + nt * 8 + 2 * c;
        float b0 = bias[col], b1 = bias[col + 1];
#pragma unroll
        for (int mt = 0; mt < 4; mt++) {
            int row = m0 + wm * 64 + mt * 16 + g;
            *(float2*)&out[(size_t)row * D_MODEL + col] =
                make_float2(acc[mt][nt][0] + b0, acc[mt][nt][1] + b1);
            *(float2*)&out[(size_t)(row + 8) * D_MODEL + col] =
                make_float2(acc[mt][nt][2] + b0, acc[mt][nt][3] + b1);
        }
    }
}

// ---------------------------------------------------------------------------
// Flash attention, split-KV, register-level S->PV handoff, and a 1-deep
// SOFTWARE PIPELINE over nt: S(nt+1) MMAs are issued BEFORE exp(nt), so exp
// consumes results that are a full iteration old (no scoreboard stall), and
// PV(nt) V-fragments are loaded just-in-time (S(nt+1) provides the overlap).
// Grid (32, 12, KV_SPLIT), 128 threads (4 warps x 32 q-rows). kv tiles of 64.
// ---------------------------------------------------------------------------
#define AST 68
#define VST2 68
#define ATT_QW   (128 * AST)
#define ATT_KW   (64 * AST)
#define ATT_VW   (64 * VST2)
#define ATT_SMEM_BYTES ((ATT_QW + 2 * ATT_KW + 2 * ATT_VW) * 4)
#define ATT_THREADS 128

__global__ void __launch_bounds__(ATT_THREADS, 2) attn_tc_kernel(
    const float* __restrict__ q, const float* __restrict__ k,
    const float* __restrict__ v, float* __restrict__ opart,
    float* __restrict__ lpart)
{
    extern __shared__ uint32_t sh[];
    uint32_t* Qp  = sh;
    uint32_t* Ksb[2] = { sh + ATT_QW, sh + ATT_QW + ATT_KW };
    uint32_t* Vsb[2] = { sh + ATT_QW + 2 * ATT_KW, sh + ATT_QW + 2 * ATT_KW + ATT_VW };

    const int tid  = threadIdx.x;
    const int wid  = tid >> 5;
    const int lane = tid & 31;
    const int g    = lane >> 2;
    const int c    = lane & 3;
    const int wr   = wid * 32;         // this warp's 32-row block
    const int h    = blockIdx.y;
    const int q0   = blockIdx.x * 128;
    const int sp   = blockIdx.z;

    float* op = opart + (size_t)sp * N_TOK * D_MODEL;
    float* lp = lpart + (size_t)sp * N_HEADS * N_TOK;

    const float* kh = k + ((size_t)h * N_TOK + sp * SPLIT_LEN) * D_K;   // [tok][dk]
    const float* vh = v + (size_t)h * D_K * N_TOK + sp * SPLIT_LEN;     // [dk][tok']

    // ldmatrix per-lane address components (bytes)
    const int m_ = lane >> 3, r_ = lane & 7;
    const uint32_t KsA0 = smem_u32(Ksb[0]), KsA1 = smem_u32(Ksb[1]);
    const uint32_t VsA0 = smem_u32(Vsb[0]), VsA1 = smem_u32(Vsb[1]);
    const uint32_t kOff = (uint32_t)(r_ * AST + 4 * m_) * 4;
    const uint32_t vOff = (uint32_t)(((m_ >> 1) * 8 + r_) * VST2 + 4 * (m_ & 1)) * 4;

    // Prefetch kv tile 0.
    {
        uint32_t ks = KsA0, vs = VsA0;
#pragma unroll
        for (int i = tid; i < 1024; i += ATT_THREADS) {
            int r = i >> 4, c4 = (i & 15) * 4;
            CP_ASYNC16(ks + (r * AST + c4) * 4, kh + (size_t)r * D_K + c4);
            CP_ASYNC16(vs + (r * VST2 + c4) * 4, vh + (size_t)r * N_TOK + c4);
        }
        CP_COMMIT();
    }

    // Q tile: already scaled + tf32 bits -> plain copy into smem (prologue only).
    const float* qh = q + ((size_t)h * N_TOK + q0) * D_K;
#pragma unroll
    for (int i = tid; i < 2048; i += ATT_THREADS) {
        int r = i >> 4, c4 = (i & 15) * 4;
        uint4 t = *(const uint4*)(qh + (size_t)r * D_K + c4);
        *(uint4*)&Qp[r * AST + c4] = t;
    }
    __syncthreads();

    // Persistent Q fragments: 2 m-tiles x 8 k-steps.
    uint32_t qa[2][8][4];
#pragma unroll
    for (int mt = 0; mt < 2; mt++) {
        int rb = wr + mt * 16;
#pragma unroll
        for (int s = 0; s < 8; s++) {
            int c0 = s * 8;
            qa[mt][s][0] = Qp[(rb + g) * AST + c0 + c];
            qa[mt][s][1] = Qp[(rb + g + 8) * AST + c0 + c];
            qa[mt][s][2] = Qp[(rb + g) * AST + c0 + c + 4];
            qa[mt][s][3] = Qp[(rb + g + 8) * AST + c0 + c + 4];
        }
    }

    float o[2][8][4];
#pragma unroll
    for (int mt = 0; mt < 2; mt++)
#pragma unroll
        for (int nt = 0; nt < 8; nt++)
#pragma unroll
            for (int f = 0; f < 4; f++) o[mt][nt][f] = 0.0f;
    float ls[4] = {0.0f, 0.0f, 0.0f, 0.0f};   // [mt*2 + (0:row g,1:row g+8)]

    const int NIT = SPLIT_LEN / 64;  // 16
    for (int it = 0; it < NIT; ++it) {
        const int cur = it & 1;
        if (it + 1 < NIT) {
            const int kt = (it + 1) * 64;
            uint32_t ks = cur ? KsA0 : KsA1;
            uint32_t vs = cur ? VsA0 : VsA1;
#pragma unroll
            for (int i = tid; i < 1024; i += ATT_THREADS) {
                int r = i >> 4, c4 = (i & 15) * 4;
                CP_ASYNC16(ks + (r * AST + c4) * 4, kh + (size_t)(kt + r) * D_K + c4);
                CP_ASYNC16(vs + (r * VST2 + c4) * 4, vh + (size_t)r * N_TOK + kt + c4);
            }
            CP_COMMIT();
            CP_WAIT1();
        } else {
            CP_WAIT0();
        }
        __syncthreads();

        const uint32_t KsA = cur ? KsA1 : KsA0;
        const uint32_t VsA = cur ? VsA1 : VsA0;

        // Tile prologue: S(0) into sC. sC index: [0]=mt0 lo-k, [1]=mt0 hi-k,
        // [2]=mt1 lo-k, [3]=mt1 hi-k (same split chains as before).
        float sC[4][4];
#pragma unroll
        for (int i = 0; i < 4; i++)
#pragma unroll
            for (int f = 0; f < 4; f++) sC[i][f] = 0.0f;
        {
            uint32_t bb[8][2];
            const uint32_t kb = KsA + kOff;
#pragma unroll
            for (int j = 0; j < 4; j++)
                ldsm_x4(bb[2 * j][0], bb[2 * j][1], bb[2 * j + 1][0], bb[2 * j + 1][1],
                        kb + (uint32_t)j * 64);
#pragma unroll
            for (int s = 0; s < 4; s++) {
                mma_tf32(sC[0], qa[0][s], bb[s]);
                mma_tf32(sC[1], qa[0][s + 4], bb[s + 4]);
                mma_tf32(sC[2], qa[1][s], bb[s]);
                mma_tf32(sC[3], qa[1][s + 4], bb[s + 4]);
            }
        }

        // Pipelined mainloop: S(nt+1) issued before exp(nt)/PV(nt).
#pragma unroll
        for (int nt = 0; nt < 8; nt++) {
            float sN[4][4];
            if (nt < 7) {
#pragma unroll
                for (int i = 0; i < 4; i++)
#pragma unroll
                    for (int f = 0; f < 4; f++) sN[i][f] = 0.0f;
                uint32_t bb[8][2];
                const uint32_t kb = KsA + kOff + (uint32_t)(nt + 1) * (8 * AST * 4);
#pragma unroll
                for (int j = 0; j < 4; j++)
                    ldsm_x4(bb[2 * j][0], bb[2 * j][1], bb[2 * j + 1][0], bb[2 * j + 1][1],
                            kb + (uint32_t)j * 64);
#pragma unroll
                for (int s = 0; s < 4; s++) {
                    mma_tf32(sN[0], qa[0][s], bb[s]);
                    mma_tf32(sN[1], qa[0][s + 4], bb[s + 4]);
                    mma_tf32(sN[2], qa[1][s], bb[s]);
                    mma_tf32(sN[3], qa[1][s + 4], bb[s + 4]);
                }
            }

            // exp2 + row sums + pack P fragments (sC is a full iter old: no stall).
            uint32_t pa[2][4];
            {
                float p0 = ex2f(sC[0][0] + sC[1][0]);
                float p1 = ex2f(sC[0][1] + sC[1][1]);
                float p2 = ex2f(sC[0][2] + sC[1][2]);
                float p3 = ex2f(sC[0][3] + sC[1][3]);
                ls[0] += p0 + p1;
                ls[1] += p2 + p3;
                pa[0][0] = f2tf32(p0); pa[0][1] = f2tf32(p2);
                pa[0][2] = f2tf32(p1); pa[0][3] = f2tf32(p3);
            }
            {
                float p0 = ex2f(sC[2][0] + sC[3][0]);
                float p1 = ex2f(sC[2][1] + sC[3][1]);
                float p2 = ex2f(sC[2][2] + sC[3][2]);
                float p3 = ex2f(sC[2][3] + sC[3][3]);
                ls[2] += p0 + p1;
                ls[3] += p2 + p3;
                pa[1][0] = f2tf32(p0); pa[1][1] = f2tf32(p2);
                pa[1][2] = f2tf32(p1); pa[1][3] = f2tf32(p3);
            }

            // PV: O += P(nt) . V(nt chunk); V B-frags loaded just-in-time.
            const uint32_t vb = VsA + vOff + (uint32_t)nt * 32;
#pragma unroll
            for (int j = 0; j < 4; j++) {
                uint32_t b0, b1, b2, b3;
                ldsm_x4(b0, b1, b2, b3, vb + (uint32_t)j * (16 * VST2 * 4));
                uint32_t bA[2] = {b0, b1}, bB[2] = {b2, b3};
#pragma unroll
                for (int mt = 0; mt < 2; mt++) {
                    mma_tf32(o[mt][2 * j], pa[mt], bA);
                    mma_tf32(o[mt][2 * j + 1], pa[mt], bB);
                }
            }

            // Rotate pipeline registers (renamed away by full unroll).
            if (nt < 7) {
#pragma unroll
                for (int i = 0; i < 4; i++)
#pragma unroll
                    for (int f = 0; f < 4; f++) sC[i][f] = sN[i][f];
            }
        }

        __syncthreads();  // all reads of buf[cur] done before next prefetch
    }

    // Row sums across the 4-lane quad; write l and O for both m-tiles.
#pragma unroll
    for (int i = 0; i < 4; i++) {
        ls[i] += __shfl_xor_sync(0xffffffffu, ls[i], 1);
        ls[i] += __shfl_xor_sync(0xffffffffu, ls[i], 2);
    }
    if (c == 0) {
#pragma unroll
        for (int mt = 0; mt < 2; mt++) {
            lp[(size_t)h * N_TOK + q0 + wr + mt * 16 + g]     = ls[mt * 2];
            lp[(size_t)h * N_TOK + q0 + wr + mt * 16 + g + 8] = ls[mt * 2 + 1];
        }
    }

#pragma unroll
    for (int mt = 0; mt < 2; mt++) {
        int rb = q0 + wr + mt * 16;
#pragma unroll
        for (int nt = 0; nt < 8; nt++) {
            int col = h * D_K + nt * 8 + 2 * c;
            *(float2*)&op[(size_t)(rb + g) * D_MODEL + col] =
                make_float2(o[mt][nt][0], o[mt][nt][1]);
            *(float2*)&op[(size_t)(rb + g + 8) * D_MODEL + col] =
                make_float2(o[mt][nt][2], o[mt][nt][3]);
        }
    }
}

// ---------------------------------------------------------------------------
// Combine: attn = tf32(sum_sp O_sp / sum_sp l_sp)
// ---------------------------------------------------------------------------
__global__ void combine_kernel(const float* __restrict__ opart,
                               const float* __restrict__ lpart,
                               float* __restrict__ out)
{
    int i = blockIdx.x * blockDim.x + threadIdx.x;   // float4 index
    if (i >= N_TOK * D_MODEL / 4) return;
    int r  = i / (D_MODEL / 4);
    int c4 = (i % (D_MODEL / 4)) * 4;
    int h  = c4 >> 6;
    float l = 0.0f;
    float4 a = make_float4(0.0f, 0.0f, 0.0f, 0.0f);
#pragma unroll
    for (int sp = 0; sp < KV_SPLIT; sp++) {
        l += lpart[(size_t)sp * N_HEADS * N_TOK + (size_t)h * N_TOK + r];
        float4 t = ((const float4*)(opart + (size_t)sp * N_TOK * D_MODEL))[i];
        a.x += t.x; a.y += t.y; a.z += t.z; a.w += t.w;
    }
    float inv = 1.0f / l;
    float4 o;
    o.x = f2tf32f(a.x * inv); o.y = f2tf32f(a.y * inv);
    o.z = f2tf32f(a.z * inv); o.w = f2tf32f(a.w * inv);
    ((float4*)out)[i] = o;
}

// ---------------------------------------------------------------------------
// Launch
// ---------------------------------------------------------------------------
extern "C" void kernel_launch(void* const* d_in, const int* in_sizes, int n_in,
                              void* d_out, int out_size)
{
    const float* Q  = (const float*)d_in[0];
    const float* K  = (const float*)d_in[1];
    const float* V  = (const float*)d_in[2];
    const float* Wq = (const float*)d_in[3];
    const float* bq = (const float*)d_in[4];
    const float* Wk = (const float*)d_in[5];
    const float* bk = (const float*)d_in[6];
    const float* Wv = (const float*)d_in[7];
    const float* bv = (const float*)d_in[8];
    const float* Wo = (const float*)d_in[9];
    const float* bo = (const float*)d_in[10];
    float* out = (float*)d_out;

    float *qb, *kb, *vb, *ab, *xc, *wc, *op, *lp;
    cudaGetSymbolAddress((void**)&qb, g_q);
    cudaGetSymbolAddress((void**)&kb, g_k);
    cudaGetSymbolAddress((void**)&vb, g_v);
    cudaGetSymbolAddress((void**)&ab, g_attn);
    cudaGetSymbolAddress((void**)&xc, g_xc);
    cudaGetSymbolAddress((void**)&wc, g_wc);
    cudaGetSymbolAddress((void**)&op, g_op);
    cudaGetSymbolAddress((void**)&lp, g_lp);

    float* xc0 = xc;
    float* xc1 = xc + (size_t)N_TOK * D_MODEL;
    float* xc2 = xc + 2 * (size_t)N_TOK * D_MODEL;
    float* wc0 = wc;
    float* wc1 = wc + (size_t)D_MODEL * D_MODEL;
    float* wc2 = wc + 2 * (size_t)D_MODEL * D_MODEL;
    float* wc3 = wc + 3 * (size_t)D_MODEL * D_MODEL;

    // Idempotent, capture-safe (not stream ops).
    cudaFuncSetAttribute(attn_tc_kernel,
                         cudaFuncAttributeMaxDynamicSharedMemorySize, ATT_SMEM_BYTES);
    cudaFuncSetAttribute(qkv_gemm_kernel,
                         cudaFuncAttributeMaxDynamicSharedMemorySize, GEMM_SMEM_BYTES);
    cudaFuncSetAttribute(gemm_o_kernel,
                         cudaFuncAttributeMaxDynamicSharedMemorySize, GEMM_SMEM_BYTES);

    // 1) Pre-convert operands to tf32 (RNA), 2 fused launches.
    dim3 cvtIGrid((NX4 + 255) / 256, 3);
    cvt_inputs_kernel<<<cvtIGrid, 256>>>((const float4*)Q, (const float4*)K,
                                         (const float4*)V, (float4*)xc);
    dim3 cvtWGrid((NW4 + 255) / 256, 4);
    cvt_weights_kernel<<<cvtWGrid, 256>>>((const float4*)Wq, (const float4*)Wk,
                                          (const float4*)Wv, (const float4*)Wo,
                                          (float4*)wc);

    // 2) Fused QKV projections (V transposed + sigma-permuted; q pre-scaled).
    dim3 qkvGrid(D_MODEL / GBN, N_TOK / GBM, 3);   // (6, 32, 3)
    qkv_gemm_kernel<<<qkvGrid, 256, GEMM_SMEM_BYTES>>>(
        xc0, xc1, xc2, wc0, wc1, wc2, bq, bk, bv, qb, kb, vb);

    // 3) Split-KV attention (128 threads, 4 warps x 32 rows).
    dim3 attnGrid(N_TOK / 128, N_HEADS, KV_SPLIT); // (32, 12, 4)
    attn_tc_kernel<<<attnGrid, ATT_THREADS, ATT_SMEM_BYTES>>>(qb, kb, vb, op, lp);

    // 4) Combine partials -> g_attn (tf32 bits).
    combine_kernel<<<(NX4 + 255) / 256, 256>>>(op, lp, ab);

    // 5) Output projection.
    dim3 oGrid(D_MODEL / GBN, N_TOK / GBM);        // (6, 32)
    gemm_o_kernel<<<oGrid, 256, GEMM_SMEM_BYTES>>>(ab, wc3, bo, out);
}